// round 2
// baseline (speedup 1.0000x reference)
#include <cuda_runtime.h>

#define N_NODES 100000
#define N_EDGES 1600000

// ---------------- scratch (__device__ globals; no allocation allowed) ----------------
__device__ float g_deg[N_NODES];
__device__ float g_dis[N_NODES];
__device__ int   g_cnt[N_NODES];      // in-degree histogram (excl. self loop)
__device__ int   g_rowptr[N_NODES];   // CSR row start (by dst)
__device__ int   g_fill[N_NODES];     // scatter cursor
__device__ int   g_src[N_EDGES];      // decoded src
__device__ int   g_dst[N_EDGES];      // decoded dst
__device__ int   g_col[N_EDGES];      // CSR: src per slot
__device__ float g_val[N_EDGES];      // CSR: norm per slot
__device__ int   g_bsum[128];
__device__ int   g_is64;
__device__ float g_W45[256 * 3];
__device__ float g_b45[3];
__device__ float g_bufA[(size_t)N_NODES * 256];
__device__ float g_bufB[(size_t)N_NODES * 256];

// ---------------- setup kernels ----------------
__global__ void k_init() {
    int i = blockIdx.x * blockDim.x + threadIdx.x;
    if (i < N_NODES) { g_deg[i] = 1.0f; g_cnt[i] = 0; }
    if (i == 0) g_is64 = 1;
}

// detect whether edge_index buffer is really int64 or actually int32.
// Read only the first N_EDGES int64 words: that spans the full buffer if it is
// int32 (2E * 4B) and the first half if it is genuine int64 — safe either way.
__global__ void k_detect(const long long* __restrict__ ei) {
    int i = blockIdx.x * blockDim.x + threadIdx.x;
    if (i < N_EDGES) {
        unsigned long long v = (unsigned long long)ei[i];
        if (v >= (unsigned long long)N_NODES) g_is64 = 0;  // racy but monotone -> deterministic
    }
}

__global__ void k_decode(const void* __restrict__ eiv) {
    int e = blockIdx.x * blockDim.x + threadIdx.x;
    if (e >= N_EDGES) return;
    if (g_is64) {
        const long long* ei = (const long long*)eiv;
        g_src[e] = (int)ei[e];
        g_dst[e] = (int)ei[N_EDGES + e];
    } else {
        const int* ei = (const int*)eiv;
        g_src[e] = ei[e];
        g_dst[e] = ei[N_EDGES + e];
    }
}

__global__ void k_deg(const float* __restrict__ ew) {
    int e = blockIdx.x * blockDim.x + threadIdx.x;
    if (e >= N_EDGES) return;
    int d = g_dst[e];
    atomicAdd(&g_deg[d], ew[e]);
    atomicAdd(&g_cnt[d], 1);
}

__global__ void k_dis() {
    int i = blockIdx.x * blockDim.x + threadIdx.x;
    if (i < N_NODES) g_dis[i] = rsqrtf(g_deg[i]);
}

// two-level exclusive scan of g_cnt -> g_rowptr
__global__ void k_scan1() {
    __shared__ int s[1024];
    int tid = threadIdx.x;
    int i = blockIdx.x * 1024 + tid;
    int v = (i < N_NODES) ? g_cnt[i] : 0;
    s[tid] = v;
    __syncthreads();
    for (int off = 1; off < 1024; off <<= 1) {
        int t = (tid >= off) ? s[tid - off] : 0;
        __syncthreads();
        s[tid] += t;
        __syncthreads();
    }
    if (i < N_NODES) g_rowptr[i] = s[tid] - v;   // exclusive within block
    if (tid == 1023) g_bsum[blockIdx.x] = s[tid];
}

__global__ void k_scan2(int nb) {
    __shared__ int s[128];
    int tid = threadIdx.x;
    int v = (tid < nb) ? g_bsum[tid] : 0;
    s[tid] = v;
    __syncthreads();
    for (int off = 1; off < 128; off <<= 1) {
        int t = (tid >= off) ? s[tid - off] : 0;
        __syncthreads();
        s[tid] += t;
        __syncthreads();
    }
    if (tid < nb) g_bsum[tid] = s[tid] - v;      // exclusive
}

__global__ void k_addoff() {
    int i = blockIdx.x * blockDim.x + threadIdx.x;
    if (i < N_NODES) {
        int r = g_rowptr[i] + g_bsum[i >> 10];
        g_rowptr[i] = r;
        g_fill[i] = r;
    }
}

__global__ void k_build(const float* __restrict__ ew) {
    int e = blockIdx.x * blockDim.x + threadIdx.x;
    if (e >= N_EDGES) return;
    int s = g_src[e], d = g_dst[e];
    float nm = g_dis[s] * ew[e] * g_dis[d];
    int p = atomicAdd(&g_fill[d], 1);
    g_col[p] = s;
    g_val[p] = nm;
}

// fold W4 @ W_out and b4 @ W_out + b_out
__global__ void k_w45(const float* __restrict__ W4, const float* __restrict__ b4,
                      const float* __restrict__ Wout, const float* __restrict__ bout) {
    int t = blockIdx.x * blockDim.x + threadIdx.x;
    if (t < 256 * 3) {
        int k = t / 3, c = t % 3;
        float s = 0.f;
        for (int j = 0; j < 256; j++) s += W4[k * 256 + j] * Wout[j * 3 + c];
        g_W45[t] = s;
    }
    if (t < 3) {
        float s = bout[t];
        for (int j = 0; j < 256; j++) s += b4[j] * Wout[j * 3 + t];
        g_b45[t] = s;
    }
}

// ---------------- dense GEMM: C[N,dout] = A[N,din] @ W[din,dout] (+bias, relu) ----------------
// 64x64 tile, BK=16, 256 threads, 4x4 per thread
__global__ void k_gemm(const float* __restrict__ A, const float* __restrict__ W,
                       const float* __restrict__ bias, float* __restrict__ C,
                       int din, int dout, int relu) {
    __shared__ float As[16][64];   // As[k][m]
    __shared__ float Bs[16][64];   // Bs[k][n]
    int tid = threadIdx.x;
    int row0 = blockIdx.x * 64;
    int col0 = blockIdx.y * 64;
    int tx = tid & 15, ty = tid >> 4;

    float acc[4][4];
#pragma unroll
    for (int i = 0; i < 4; i++)
#pragma unroll
        for (int j = 0; j < 4; j++) acc[i][j] = 0.f;

    for (int k0 = 0; k0 < din; k0 += 16) {
#pragma unroll
        for (int i = 0; i < 4; i++) {
            int idx = tid + i * 256;
            int r = idx >> 4, c = idx & 15;     // A[row0+r][k0+c]
            float v = (row0 + r < N_NODES) ? A[(size_t)(row0 + r) * din + k0 + c] : 0.f;
            As[c][r] = v;
        }
#pragma unroll
        for (int i = 0; i < 4; i++) {
            int idx = tid + i * 256;
            int r = idx >> 6, c = idx & 63;     // W[k0+r][col0+c]
            Bs[r][c] = W[(size_t)(k0 + r) * dout + col0 + c];
        }
        __syncthreads();
#pragma unroll
        for (int k = 0; k < 16; k++) {
            float4 a4 = *(const float4*)&As[k][ty * 4];
            float4 b4 = *(const float4*)&Bs[k][tx * 4];
            float a[4] = {a4.x, a4.y, a4.z, a4.w};
            float b[4] = {b4.x, b4.y, b4.z, b4.w};
#pragma unroll
            for (int i = 0; i < 4; i++)
#pragma unroll
                for (int j = 0; j < 4; j++) acc[i][j] += a[i] * b[j];
        }
        __syncthreads();
    }

#pragma unroll
    for (int i = 0; i < 4; i++) {
        int r = row0 + ty * 4 + i;
        if (r >= N_NODES) continue;
#pragma unroll
        for (int j = 0; j < 4; j++) {
            int c = col0 + tx * 4 + j;
            float v = acc[i][j];
            if (bias) v += bias[c];
            if (relu) v = fmaxf(v, 0.f);
            C[(size_t)r * dout + c] = v;
        }
    }
}

// ---------------- aggregation: out[v] = sum_{e in CSR(v)} norm_e * H[src_e] + H[v]*dis[v]^2 ----------------
template <int D, bool BIAS, bool RELU>
__global__ void k_agg(const float* __restrict__ H, const float* __restrict__ bias,
                      float* __restrict__ out) {
    int warp = (blockIdx.x * blockDim.x + threadIdx.x) >> 5;
    int lane = threadIdx.x & 31;
    if (warp >= N_NODES) return;
    constexpr int R = D / 32;
    float acc[R];
    float selfn = g_dis[warp];
    selfn = selfn * selfn;
    const float* hv = H + (size_t)warp * D;
#pragma unroll
    for (int k = 0; k < R; k++) acc[k] = hv[lane + 32 * k] * selfn;

    int s = g_rowptr[warp];
    int e = s + g_cnt[warp];
    for (int p = s; p < e; p++) {
        int src = __ldg(&g_col[p]);
        float w = __ldg(&g_val[p]);
        const float* hs = H + (size_t)src * D;
#pragma unroll
        for (int k = 0; k < R; k++) acc[k] += __ldg(&hs[lane + 32 * k]) * w;
    }

    float* o = out + (size_t)warp * D;
#pragma unroll
    for (int k = 0; k < R; k++) {
        float v = acc[k];
        if (BIAS) v += bias[lane + 32 * k];
        if (RELU) v = fmaxf(v, 0.f);
        o[lane + 32 * k] = v;
    }
}

// ---------------- narrow output GEMM: out[N,3] = A[N,256] @ W45 + b45 ----------------
__global__ void k_out(const float* __restrict__ A, float* __restrict__ out) {
    int warp = (blockIdx.x * blockDim.x + threadIdx.x) >> 5;
    int lane = threadIdx.x & 31;
    if (warp >= N_NODES) return;
    const float* a = A + (size_t)warp * 256;
    float s0 = 0.f, s1 = 0.f, s2 = 0.f;
#pragma unroll
    for (int k = 0; k < 8; k++) {
        int j = lane + 32 * k;
        float v = a[j];
        s0 += v * g_W45[j * 3 + 0];
        s1 += v * g_W45[j * 3 + 1];
        s2 += v * g_W45[j * 3 + 2];
    }
#pragma unroll
    for (int off = 16; off; off >>= 1) {
        s0 += __shfl_down_sync(0xffffffffu, s0, off);
        s1 += __shfl_down_sync(0xffffffffu, s1, off);
        s2 += __shfl_down_sync(0xffffffffu, s2, off);
    }
    if (lane == 0) {
        out[(size_t)warp * 3 + 0] = s0 + g_b45[0];
        out[(size_t)warp * 3 + 1] = s1 + g_b45[1];
        out[(size_t)warp * 3 + 2] = s2 + g_b45[2];
    }
}

// ---------------- launch ----------------
extern "C" void kernel_launch(void* const* d_in, const int* in_sizes, int n_in,
                              void* d_out, int out_size) {
    const float* x    = (const float*)d_in[0];
    const void*  ei   = d_in[1];
    const float* ew   = (const float*)d_in[2];
    const float* W1   = (const float*)d_in[3];
    const float* b1   = (const float*)d_in[4];
    const float* W2   = (const float*)d_in[5];
    const float* b2   = (const float*)d_in[6];
    const float* W3   = (const float*)d_in[7];
    const float* b3   = (const float*)d_in[8];
    const float* W4   = (const float*)d_in[9];
    const float* b4   = (const float*)d_in[10];
    const float* Wout = (const float*)d_in[11];
    const float* bout = (const float*)d_in[12];
    float* out = (float*)d_out;

    // Resolve device addresses of __device__ scratch buffers (host cannot use
    // the symbol name directly as a pointer argument).
    float* bufA = nullptr;
    float* bufB = nullptr;
    cudaGetSymbolAddress((void**)&bufA, g_bufA);
    cudaGetSymbolAddress((void**)&bufB, g_bufB);

    const int TB = 256;
    int nodeBlocks = (N_NODES + TB - 1) / TB;
    int edgeBlocks = (N_EDGES + TB - 1) / TB;
    int scanBlocks = (N_NODES + 1023) / 1024;           // 98
    int warpNodeBlocks = (N_NODES + 7) / 8;             // warp per node, 8 warps/block

    // graph preprocessing (rebuilt every replay; deterministic up to fp atomic order)
    k_init<<<nodeBlocks, TB>>>();
    k_detect<<<(N_EDGES + TB - 1) / TB, TB>>>((const long long*)ei);
    k_decode<<<edgeBlocks, TB>>>(ei);
    k_deg<<<edgeBlocks, TB>>>(ew);
    k_dis<<<nodeBlocks, TB>>>();
    k_scan1<<<scanBlocks, 1024>>>();
    k_scan2<<<1, 128>>>(scanBlocks);
    k_addoff<<<nodeBlocks, TB>>>();
    k_build<<<edgeBlocks, TB>>>(ew);
    k_w45<<<1, 768>>>(W4, b4, Wout, bout);

    dim3 g1((N_NODES + 63) / 64, 1);
    dim3 g2((N_NODES + 63) / 64, 2);
    dim3 g4((N_NODES + 63) / 64, 4);

    // L1: h1 = relu(agg(x @ W1) + b1)          [aggregate at 64]
    k_gemm<<<g1, 256>>>(x, W1, nullptr, bufA, 128, 64, 0);
    k_agg<64, true, true><<<warpNodeBlocks, 256>>>(bufA, b1, bufB);

    // L2: h2 = relu(agg(h1) @ W2 + b2)         [aggregate at 64]
    k_agg<64, false, false><<<warpNodeBlocks, 256>>>(bufB, nullptr, bufA);
    k_gemm<<<g2, 256>>>(bufA, W2, b2, bufB, 64, 128, 1);

    // L3: h3 = relu(agg(h2) @ W3 + b3)         [aggregate at 128]
    k_agg<128, false, false><<<warpNodeBlocks, 256>>>(bufB, nullptr, bufA);
    k_gemm<<<g4, 256>>>(bufA, W3, b3, bufB, 128, 256, 1);

    // L4 + head: out = agg(h3) @ (W4·Wout) + (b4·Wout + bout)   [aggregate at 256]
    k_agg<256, false, false><<<warpNodeBlocks, 256>>>(bufB, nullptr, bufA);
    k_out<<<warpNodeBlocks, 256>>>(bufA, out);

    (void)in_sizes; (void)n_in; (void)out_size;
}

// round 3
// speedup vs baseline: 1.3748x; 1.3748x over previous
#include <cuda_runtime.h>

#define N_NODES 100000
#define N_EDGES 1600000

typedef unsigned long long ull;

// ---------------- scratch (__device__ globals; no allocation allowed) ----------------
__device__ float g_deg[N_NODES];
__device__ float g_dis[N_NODES];
__device__ int   g_cnt[N_NODES];
__device__ int   g_rowptr[N_NODES];
__device__ int   g_fill[N_NODES];
__device__ int   g_src[N_EDGES];
__device__ int   g_dst[N_EDGES];
__device__ int   g_col[N_EDGES];
__device__ float g_val[N_EDGES];
__device__ int   g_bsum[128];
__device__ int   g_is64;
__device__ float g_W45[256 * 3];
__device__ float g_b45[3];
__device__ float g_bufA[(size_t)N_NODES * 256];
__device__ float g_bufB[(size_t)N_NODES * 256];

// ---------------- f32x2 packed helpers ----------------
__device__ __forceinline__ ull bcast2(float x) {
    ull r; asm("mov.b64 %0, {%1, %1};" : "=l"(r) : "f"(x)); return r;
}
__device__ __forceinline__ void fma2(ull& d, ull a, ull b) {
    asm("fma.rn.f32x2 %0, %1, %2, %0;" : "+l"(d) : "l"(a), "l"(b));
}
__device__ __forceinline__ void unpack2(ull v, float& lo, float& hi) {
    asm("mov.b64 {%0, %1}, %2;" : "=f"(lo), "=f"(hi) : "l"(v));
}

// ---------------- setup kernels ----------------
__global__ void k_init() {
    int i = blockIdx.x * blockDim.x + threadIdx.x;
    if (i < N_NODES) { g_deg[i] = 1.0f; g_cnt[i] = 0; }
    if (i == 0) g_is64 = 1;
}

// int64 vs int32 detection: scan first N_EDGES int64 words (safe for both dtypes)
__global__ void k_detect(const long long* __restrict__ ei) {
    int i = blockIdx.x * blockDim.x + threadIdx.x;
    if (i < N_EDGES) {
        unsigned long long v = (unsigned long long)ei[i];
        if (v >= (unsigned long long)N_NODES) g_is64 = 0;
    }
}

// fused decode + weighted-degree histogram
__global__ void k_decdeg(const void* __restrict__ eiv, const float* __restrict__ ew) {
    int e = blockIdx.x * blockDim.x + threadIdx.x;
    if (e >= N_EDGES) return;
    int s, d;
    if (g_is64) {
        const long long* ei = (const long long*)eiv;
        s = (int)ei[e];
        d = (int)ei[N_EDGES + e];
    } else {
        const int* ei = (const int*)eiv;
        s = ei[e];
        d = ei[N_EDGES + e];
    }
    g_src[e] = s;
    g_dst[e] = d;
    atomicAdd(&g_deg[d], ew[e]);
    atomicAdd(&g_cnt[d], 1);
}

__global__ void k_dis() {
    int i = blockIdx.x * blockDim.x + threadIdx.x;
    if (i < N_NODES) g_dis[i] = rsqrtf(g_deg[i]);
}

__global__ void k_scan1() {
    __shared__ int s[1024];
    int tid = threadIdx.x;
    int i = blockIdx.x * 1024 + tid;
    int v = (i < N_NODES) ? g_cnt[i] : 0;
    s[tid] = v;
    __syncthreads();
    for (int off = 1; off < 1024; off <<= 1) {
        int t = (tid >= off) ? s[tid - off] : 0;
        __syncthreads();
        s[tid] += t;
        __syncthreads();
    }
    if (i < N_NODES) g_rowptr[i] = s[tid] - v;
    if (tid == 1023) g_bsum[blockIdx.x] = s[tid];
}

__global__ void k_scan2(int nb) {
    __shared__ int s[128];
    int tid = threadIdx.x;
    int v = (tid < nb) ? g_bsum[tid] : 0;
    s[tid] = v;
    __syncthreads();
    for (int off = 1; off < 128; off <<= 1) {
        int t = (tid >= off) ? s[tid - off] : 0;
        __syncthreads();
        s[tid] += t;
        __syncthreads();
    }
    if (tid < nb) g_bsum[tid] = s[tid] - v;
}

__global__ void k_addoff() {
    int i = blockIdx.x * blockDim.x + threadIdx.x;
    if (i < N_NODES) {
        int r = g_rowptr[i] + g_bsum[i >> 10];
        g_rowptr[i] = r;
        g_fill[i] = r;
    }
}

__global__ void k_build(const float* __restrict__ ew) {
    int e = blockIdx.x * blockDim.x + threadIdx.x;
    if (e >= N_EDGES) return;
    int s = g_src[e], d = g_dst[e];
    float nm = g_dis[s] * ew[e] * g_dis[d];
    int p = atomicAdd(&g_fill[d], 1);
    g_col[p] = s;
    g_val[p] = nm;
}

__global__ void k_w45(const float* __restrict__ W4, const float* __restrict__ b4,
                      const float* __restrict__ Wout, const float* __restrict__ bout) {
    int t = blockIdx.x * blockDim.x + threadIdx.x;
    if (t < 256 * 3) {
        int k = t / 3, c = t % 3;
        float s = 0.f;
        for (int j = 0; j < 256; j++) s += W4[k * 256 + j] * Wout[j * 3 + c];
        g_W45[t] = s;
    }
    if (t < 3) {
        float s = bout[t];
        for (int j = 0; j < 256; j++) s += b4[j] * Wout[j * 3 + t];
        g_b45[t] = s;
    }
}

// ---------------- dense GEMM via f32x2: C[N,dout] = A[N,din] @ W[din,dout] ----------------
// tile 128(M) x 64(N), BK=16, 256 threads, 8x4 microtile, packed-pair accumulators
__global__ void k_gemm(const float* __restrict__ A, const float* __restrict__ W,
                       const float* __restrict__ bias, float* __restrict__ C,
                       int din, int dout, int relu) {
    __shared__ float As[16][132];   // As[k][m], pad keeps 16B alignment & low STS conflicts
    __shared__ float Bs[16][64];    // Bs[k][n]
    int tid = threadIdx.x;
    int row0 = blockIdx.x * 128;
    int col0 = blockIdx.y * 64;
    int tx = tid & 15;              // n block: 4 cols
    int ty = tid >> 4;              // m block: 8 rows

    ull acc[8][2];
#pragma unroll
    for (int i = 0; i < 8; i++) { acc[i][0] = 0ull; acc[i][1] = 0ull; }

    for (int k0 = 0; k0 < din; k0 += 16) {
        // A tile: 128 rows x 16 k = 512 float4; 2 per thread
#pragma unroll
        for (int i = 0; i < 2; i++) {
            int idx = tid + i * 256;
            int r = idx >> 2, c = idx & 3;
            float4 v = make_float4(0.f, 0.f, 0.f, 0.f);
            if (row0 + r < N_NODES)
                v = *(const float4*)&A[(size_t)(row0 + r) * din + k0 + c * 4];
            As[c * 4 + 0][r] = v.x;
            As[c * 4 + 1][r] = v.y;
            As[c * 4 + 2][r] = v.z;
            As[c * 4 + 3][r] = v.w;
        }
        // B tile: 16 k x 64 n = 256 float4; 1 per thread
        {
            int r = tid >> 4, c = tid & 15;
            *(float4*)&Bs[r][c * 4] = *(const float4*)&W[(size_t)(k0 + r) * dout + col0 + c * 4];
        }
        __syncthreads();
#pragma unroll
        for (int k = 0; k < 16; k++) {
            float4 a0 = *(const float4*)&As[k][ty * 8];
            float4 a1 = *(const float4*)&As[k][ty * 8 + 4];
            const ull* bp = (const ull*)&Bs[k][tx * 4];
            ull b0 = bp[0], b1 = bp[1];
            float am[8] = {a0.x, a0.y, a0.z, a0.w, a1.x, a1.y, a1.z, a1.w};
#pragma unroll
            for (int i = 0; i < 8; i++) {
                ull ab = bcast2(am[i]);
                fma2(acc[i][0], ab, b0);
                fma2(acc[i][1], ab, b1);
            }
        }
        __syncthreads();
    }

#pragma unroll
    for (int i = 0; i < 8; i++) {
        int r = row0 + ty * 8 + i;
        if (r >= N_NODES) continue;
        float4 v;
        unpack2(acc[i][0], v.x, v.y);
        unpack2(acc[i][1], v.z, v.w);
        int c = col0 + tx * 4;
        if (bias) {
            v.x += bias[c];
            v.y += bias[c + 1];
            v.z += bias[c + 2];
            v.w += bias[c + 3];
        }
        if (relu) {
            v.x = fmaxf(v.x, 0.f); v.y = fmaxf(v.y, 0.f);
            v.z = fmaxf(v.z, 0.f); v.w = fmaxf(v.w, 0.f);
        }
        *(float4*)&C[(size_t)r * dout + c] = v;
    }
}

// ---------------- aggregation D=64: 2 edges per warp (half-warp each), float4 ----------------
template <bool BIAS, bool RELU>
__global__ void k_agg64(const float* __restrict__ H, const float* __restrict__ bias,
                        float* __restrict__ out) {
    int warp = (blockIdx.x * blockDim.x + threadIdx.x) >> 5;
    int lane = threadIdx.x & 31;
    if (warp >= N_NODES) return;
    int half = lane >> 4, hl = lane & 15;
    const float4* H4 = (const float4*)H;

    float4 acc = make_float4(0.f, 0.f, 0.f, 0.f);
    if (half == 0) {
        float selfn = g_dis[warp];
        selfn *= selfn;
        float4 v = H4[(size_t)warp * 16 + hl];
        acc.x = v.x * selfn; acc.y = v.y * selfn;
        acc.z = v.z * selfn; acc.w = v.w * selfn;
    }
    int s = g_rowptr[warp];
    int e = s + g_cnt[warp];
    for (int p = s + half; p < e; p += 2) {
        int src = __ldg(&g_col[p]);
        float w = __ldg(&g_val[p]);
        float4 v = __ldg(&H4[(size_t)src * 16 + hl]);
        acc.x += v.x * w; acc.y += v.y * w;
        acc.z += v.z * w; acc.w += v.w * w;
    }
    __syncwarp();
    acc.x += __shfl_xor_sync(0xffffffffu, acc.x, 16);
    acc.y += __shfl_xor_sync(0xffffffffu, acc.y, 16);
    acc.z += __shfl_xor_sync(0xffffffffu, acc.z, 16);
    acc.w += __shfl_xor_sync(0xffffffffu, acc.w, 16);
    if (half == 0) {
        if (BIAS) {
            float4 b = ((const float4*)bias)[hl];
            acc.x += b.x; acc.y += b.y; acc.z += b.z; acc.w += b.w;
        }
        if (RELU) {
            acc.x = fmaxf(acc.x, 0.f); acc.y = fmaxf(acc.y, 0.f);
            acc.z = fmaxf(acc.z, 0.f); acc.w = fmaxf(acc.w, 0.f);
        }
        ((float4*)out)[(size_t)warp * 16 + hl] = acc;
    }
}

// ---------------- aggregation D=128: 1 float4 per lane ----------------
__global__ void k_agg128(const float* __restrict__ H, float* __restrict__ out) {
    int warp = (blockIdx.x * blockDim.x + threadIdx.x) >> 5;
    int lane = threadIdx.x & 31;
    if (warp >= N_NODES) return;
    const float4* H4 = (const float4*)H;

    float selfn = g_dis[warp];
    selfn *= selfn;
    float4 v = H4[(size_t)warp * 32 + lane];
    float4 acc = make_float4(v.x * selfn, v.y * selfn, v.z * selfn, v.w * selfn);

    int s = g_rowptr[warp];
    int e = s + g_cnt[warp];
    for (int p = s; p < e; p++) {
        int src = __ldg(&g_col[p]);
        float w = __ldg(&g_val[p]);
        float4 h = __ldg(&H4[(size_t)src * 32 + lane]);
        acc.x += h.x * w; acc.y += h.y * w;
        acc.z += h.z * w; acc.w += h.w * w;
    }
    ((float4*)out)[(size_t)warp * 32 + lane] = acc;
}

// ---------------- aggregation D=256 fused with 256->3 projection ----------------
__global__ void k_agg_out(const float* __restrict__ H, float* __restrict__ out) {
    int warp = (blockIdx.x * blockDim.x + threadIdx.x) >> 5;
    int lane = threadIdx.x & 31;
    if (warp >= N_NODES) return;
    const float4* H4 = (const float4*)H;

    float selfn = g_dis[warp];
    selfn *= selfn;
    float4 acc[2];
#pragma unroll
    for (int v = 0; v < 2; v++) {
        float4 h = H4[(size_t)warp * 64 + lane + v * 32];
        acc[v] = make_float4(h.x * selfn, h.y * selfn, h.z * selfn, h.w * selfn);
    }

    int s = g_rowptr[warp];
    int e = s + g_cnt[warp];
    for (int p = s; p < e; p++) {
        int src = __ldg(&g_col[p]);
        float w = __ldg(&g_val[p]);
#pragma unroll
        for (int v = 0; v < 2; v++) {
            float4 h = __ldg(&H4[(size_t)src * 64 + lane + v * 32]);
            acc[v].x += h.x * w; acc[v].y += h.y * w;
            acc[v].z += h.z * w; acc[v].w += h.w * w;
        }
    }

    // project: cols = 4*lane + 128*v + j
    float s0 = 0.f, s1 = 0.f, s2 = 0.f;
#pragma unroll
    for (int v = 0; v < 2; v++) {
        float a[4] = {acc[v].x, acc[v].y, acc[v].z, acc[v].w};
#pragma unroll
        for (int j = 0; j < 4; j++) {
            int col = 4 * lane + 128 * v + j;
            s0 += a[j] * g_W45[col * 3 + 0];
            s1 += a[j] * g_W45[col * 3 + 1];
            s2 += a[j] * g_W45[col * 3 + 2];
        }
    }
#pragma unroll
    for (int off = 16; off; off >>= 1) {
        s0 += __shfl_down_sync(0xffffffffu, s0, off);
        s1 += __shfl_down_sync(0xffffffffu, s1, off);
        s2 += __shfl_down_sync(0xffffffffu, s2, off);
    }
    if (lane == 0) {
        out[(size_t)warp * 3 + 0] = s0 + g_b45[0];
        out[(size_t)warp * 3 + 1] = s1 + g_b45[1];
        out[(size_t)warp * 3 + 2] = s2 + g_b45[2];
    }
}

// ---------------- launch ----------------
extern "C" void kernel_launch(void* const* d_in, const int* in_sizes, int n_in,
                              void* d_out, int out_size) {
    const float* x    = (const float*)d_in[0];
    const void*  ei   = d_in[1];
    const float* ew   = (const float*)d_in[2];
    const float* W1   = (const float*)d_in[3];
    const float* b1   = (const float*)d_in[4];
    const float* W2   = (const float*)d_in[5];
    const float* b2   = (const float*)d_in[6];
    const float* W3   = (const float*)d_in[7];
    const float* b3   = (const float*)d_in[8];
    const float* W4   = (const float*)d_in[9];
    const float* b4   = (const float*)d_in[10];
    const float* Wout = (const float*)d_in[11];
    const float* bout = (const float*)d_in[12];
    float* out = (float*)d_out;

    float* bufA = nullptr;
    float* bufB = nullptr;
    cudaGetSymbolAddress((void**)&bufA, g_bufA);
    cudaGetSymbolAddress((void**)&bufB, g_bufB);

    const int TB = 256;
    int nodeBlocks = (N_NODES + TB - 1) / TB;
    int edgeBlocks = (N_EDGES + TB - 1) / TB;
    int scanBlocks = (N_NODES + 1023) / 1024;
    int warpNodeBlocks = (N_NODES + 7) / 8;

    k_init<<<nodeBlocks, TB>>>();
    k_detect<<<(N_EDGES + TB - 1) / TB, TB>>>((const long long*)ei);
    k_decdeg<<<edgeBlocks, TB>>>(ei, ew);
    k_dis<<<nodeBlocks, TB>>>();
    k_scan1<<<scanBlocks, 1024>>>();
    k_scan2<<<1, 128>>>(scanBlocks);
    k_addoff<<<nodeBlocks, TB>>>();
    k_build<<<edgeBlocks, TB>>>(ew);
    k_w45<<<1, 768>>>(W4, b4, Wout, bout);

    int gm = (N_NODES + 127) / 128;   // 782

    // L1: h1 = relu(agg(x @ W1) + b1)        [aggregate at 64]
    k_gemm<<<dim3(gm, 1), 256>>>(x, W1, nullptr, bufA, 128, 64, 0);
    k_agg64<true, true><<<warpNodeBlocks, 256>>>(bufA, b1, bufB);

    // L2: h2 = relu(agg(h1) @ W2 + b2)       [aggregate at 64]
    k_agg64<false, false><<<warpNodeBlocks, 256>>>(bufB, nullptr, bufA);
    k_gemm<<<dim3(gm, 2), 256>>>(bufA, W2, b2, bufB, 64, 128, 1);

    // L3: h3 = relu(agg(h2) @ W3 + b3)       [aggregate at 128]
    k_agg128<<<warpNodeBlocks, 256>>>(bufB, bufA);
    k_gemm<<<dim3(gm, 4), 256>>>(bufA, W3, b3, bufB, 128, 256, 1);

    // L4 + head: out = agg(h3) @ (W4·Wout) + (b4·Wout + bout)   [aggregate at 256, fused proj]
    k_agg_out<<<warpNodeBlocks, 256>>>(bufB, out);

    (void)in_sizes; (void)n_in; (void)out_size;
}

// round 4
// speedup vs baseline: 1.5337x; 1.1156x over previous
#include <cuda_runtime.h>

#define N_NODES 100000
#define N_EDGES 1600000

typedef unsigned long long ull;

// ---------------- scratch (__device__ globals; no allocation allowed) ----------------
__device__ float g_deg[N_NODES];
__device__ float g_dis[N_NODES];
__device__ int   g_cnt[N_NODES];
__device__ int   g_rowptr[N_NODES];
__device__ int   g_fill[N_NODES];
__device__ int   g_col[N_EDGES];
__device__ float g_val[N_EDGES];
__device__ int   g_bsum[128];
__device__ int   g_is64;
__device__ float g_W45[256 * 3];
__device__ float g_b45[3];
__device__ float g_bufA[(size_t)N_NODES * 256];
__device__ float g_bufB[(size_t)N_NODES * 256];
__device__ float4 g_proj[N_NODES];

// ---------------- f32x2 packed helpers ----------------
__device__ __forceinline__ ull bcast2(float x) {
    ull r; asm("mov.b64 %0, {%1, %1};" : "=l"(r) : "f"(x)); return r;
}
__device__ __forceinline__ void fma2(ull& d, ull a, ull b) {
    asm("fma.rn.f32x2 %0, %1, %2, %0;" : "+l"(d) : "l"(a), "l"(b));
}
__device__ __forceinline__ void unpack2(ull v, float& lo, float& hi) {
    asm("mov.b64 {%0, %1}, %2;" : "=f"(lo), "=f"(hi) : "l"(v));
}

// ---------------- setup kernels ----------------
__global__ void k_init() {
    int i = blockIdx.x * blockDim.x + threadIdx.x;
    if (i < N_NODES) { g_deg[i] = 1.0f; g_cnt[i] = 0; }
    if (i == 0) g_is64 = 1;
}

// int64 vs int32 detection: scan first N_EDGES int64 words (safe for both dtypes)
__global__ void k_detect(const long long* __restrict__ ei) {
    int i = blockIdx.x * blockDim.x + threadIdx.x;
    if (i < N_EDGES) {
        unsigned long long v = (unsigned long long)ei[i];
        if (v >= (unsigned long long)N_NODES) g_is64 = 0;
    }
}

__device__ __forceinline__ void decode_edge(const void* eiv, int e, int& s, int& d) {
    if (g_is64) {
        const long long* ei = (const long long*)eiv;
        s = (int)ei[e];
        d = (int)ei[N_EDGES + e];
    } else {
        const int* ei = (const int*)eiv;
        s = ei[e];
        d = ei[N_EDGES + e];
    }
}

// decode + weighted-degree histogram (no staging arrays)
__global__ void k_decdeg(const void* __restrict__ eiv, const float* __restrict__ ew) {
    int e = blockIdx.x * blockDim.x + threadIdx.x;
    if (e >= N_EDGES) return;
    int s, d;
    decode_edge(eiv, e, s, d);
    atomicAdd(&g_deg[d], ew[e]);
    atomicAdd(&g_cnt[d], 1);
}

__global__ void k_dis() {
    int i = blockIdx.x * blockDim.x + threadIdx.x;
    if (i < N_NODES) g_dis[i] = rsqrtf(g_deg[i]);
}

__global__ void k_scan1() {
    __shared__ int s[1024];
    int tid = threadIdx.x;
    int i = blockIdx.x * 1024 + tid;
    int v = (i < N_NODES) ? g_cnt[i] : 0;
    s[tid] = v;
    __syncthreads();
    for (int off = 1; off < 1024; off <<= 1) {
        int t = (tid >= off) ? s[tid - off] : 0;
        __syncthreads();
        s[tid] += t;
        __syncthreads();
    }
    if (i < N_NODES) g_rowptr[i] = s[tid] - v;
    if (tid == 1023) g_bsum[blockIdx.x] = s[tid];
}

__global__ void k_scan2(int nb) {
    __shared__ int s[128];
    int tid = threadIdx.x;
    int v = (tid < nb) ? g_bsum[tid] : 0;
    s[tid] = v;
    __syncthreads();
    for (int off = 1; off < 128; off <<= 1) {
        int t = (tid >= off) ? s[tid - off] : 0;
        __syncthreads();
        s[tid] += t;
        __syncthreads();
    }
    if (tid < nb) g_bsum[tid] = s[tid] - v;
}

__global__ void k_addoff() {
    int i = blockIdx.x * blockDim.x + threadIdx.x;
    if (i < N_NODES) {
        int r = g_rowptr[i] + g_bsum[i >> 10];
        g_rowptr[i] = r;
        g_fill[i] = r;
    }
}

__global__ void k_build(const void* __restrict__ eiv, const float* __restrict__ ew) {
    int e = blockIdx.x * blockDim.x + threadIdx.x;
    if (e >= N_EDGES) return;
    int s, d;
    decode_edge(eiv, e, s, d);
    float nm = g_dis[s] * ew[e] * g_dis[d];
    int p = atomicAdd(&g_fill[d], 1);
    g_col[p] = s;
    g_val[p] = nm;
}

__global__ void k_w45(const float* __restrict__ W4, const float* __restrict__ b4,
                      const float* __restrict__ Wout, const float* __restrict__ bout) {
    int t = blockIdx.x * blockDim.x + threadIdx.x;
    if (t < 256 * 3) {
        int k = t / 3, c = t % 3;
        float s = 0.f;
        for (int j = 0; j < 256; j++) s += W4[k * 256 + j] * Wout[j * 3 + c];
        g_W45[t] = s;
    }
    if (t < 3) {
        float s = bout[t];
        for (int j = 0; j < 256; j++) s += b4[j] * Wout[j * 3 + t];
        g_b45[t] = s;
    }
}

// ---------------- dense GEMM via f32x2: C[N,dout] = A[N,din] @ W[din,dout] ----------------
// tile 128(M) x 64(N), BK=16, 256 threads, 8x4 microtile, packed-pair accumulators
__global__ void k_gemm(const float* __restrict__ A, const float* __restrict__ W,
                       const float* __restrict__ bias, float* __restrict__ C,
                       int din, int dout, int relu) {
    __shared__ float As[16][132];
    __shared__ float Bs[16][64];
    int tid = threadIdx.x;
    int row0 = blockIdx.x * 128;
    int col0 = blockIdx.y * 64;
    int tx = tid & 15;
    int ty = tid >> 4;

    ull acc[8][2];
#pragma unroll
    for (int i = 0; i < 8; i++) { acc[i][0] = 0ull; acc[i][1] = 0ull; }

    for (int k0 = 0; k0 < din; k0 += 16) {
#pragma unroll
        for (int i = 0; i < 2; i++) {
            int idx = tid + i * 256;
            int r = idx >> 2, c = idx & 3;
            float4 v = make_float4(0.f, 0.f, 0.f, 0.f);
            if (row0 + r < N_NODES)
                v = *(const float4*)&A[(size_t)(row0 + r) * din + k0 + c * 4];
            As[c * 4 + 0][r] = v.x;
            As[c * 4 + 1][r] = v.y;
            As[c * 4 + 2][r] = v.z;
            As[c * 4 + 3][r] = v.w;
        }
        {
            int r = tid >> 4, c = tid & 15;
            *(float4*)&Bs[r][c * 4] = *(const float4*)&W[(size_t)(k0 + r) * dout + col0 + c * 4];
        }
        __syncthreads();
#pragma unroll
        for (int k = 0; k < 16; k++) {
            float4 a0 = *(const float4*)&As[k][ty * 8];
            float4 a1 = *(const float4*)&As[k][ty * 8 + 4];
            const ull* bp = (const ull*)&Bs[k][tx * 4];
            ull b0 = bp[0], b1 = bp[1];
            float am[8] = {a0.x, a0.y, a0.z, a0.w, a1.x, a1.y, a1.z, a1.w};
#pragma unroll
            for (int i = 0; i < 8; i++) {
                ull ab = bcast2(am[i]);
                fma2(acc[i][0], ab, b0);
                fma2(acc[i][1], ab, b1);
            }
        }
        __syncthreads();
    }

#pragma unroll
    for (int i = 0; i < 8; i++) {
        int r = row0 + ty * 8 + i;
        if (r >= N_NODES) continue;
        float4 v;
        unpack2(acc[i][0], v.x, v.y);
        unpack2(acc[i][1], v.z, v.w);
        int c = col0 + tx * 4;
        if (bias) {
            v.x += bias[c];
            v.y += bias[c + 1];
            v.z += bias[c + 2];
            v.w += bias[c + 3];
        }
        if (relu) {
            v.x = fmaxf(v.x, 0.f); v.y = fmaxf(v.y, 0.f);
            v.z = fmaxf(v.z, 0.f); v.w = fmaxf(v.w, 0.f);
        }
        *(float4*)&C[(size_t)r * dout + c] = v;
    }
}

// ---------------- aggregation D=64: 2 edges per warp (half-warp each), float4 ----------------
template <bool BIAS, bool RELU>
__global__ void k_agg64(const float* __restrict__ H, const float* __restrict__ bias,
                        float* __restrict__ out) {
    int warp = (blockIdx.x * blockDim.x + threadIdx.x) >> 5;
    int lane = threadIdx.x & 31;
    if (warp >= N_NODES) return;
    int half = lane >> 4, hl = lane & 15;
    const float4* H4 = (const float4*)H;

    float4 acc = make_float4(0.f, 0.f, 0.f, 0.f);
    if (half == 0) {
        float selfn = g_dis[warp];
        selfn *= selfn;
        float4 v = H4[(size_t)warp * 16 + hl];
        acc.x = v.x * selfn; acc.y = v.y * selfn;
        acc.z = v.z * selfn; acc.w = v.w * selfn;
    }
    int s = g_rowptr[warp];
    int e = s + g_cnt[warp];
    for (int p = s + half; p < e; p += 2) {
        int src = __ldg(&g_col[p]);
        float w = __ldg(&g_val[p]);
        float4 v = __ldg(&H4[(size_t)src * 16 + hl]);
        acc.x += v.x * w; acc.y += v.y * w;
        acc.z += v.z * w; acc.w += v.w * w;
    }
    __syncwarp();
    acc.x += __shfl_xor_sync(0xffffffffu, acc.x, 16);
    acc.y += __shfl_xor_sync(0xffffffffu, acc.y, 16);
    acc.z += __shfl_xor_sync(0xffffffffu, acc.z, 16);
    acc.w += __shfl_xor_sync(0xffffffffu, acc.w, 16);
    if (half == 0) {
        if (BIAS) {
            float4 b = ((const float4*)bias)[hl];
            acc.x += b.x; acc.y += b.y; acc.z += b.z; acc.w += b.w;
        }
        if (RELU) {
            acc.x = fmaxf(acc.x, 0.f); acc.y = fmaxf(acc.y, 0.f);
            acc.z = fmaxf(acc.z, 0.f); acc.w = fmaxf(acc.w, 0.f);
        }
        ((float4*)out)[(size_t)warp * 16 + hl] = acc;
    }
}

// ---------------- aggregation D=128: 1 float4 per lane ----------------
__global__ void k_agg128(const float* __restrict__ H, float* __restrict__ out) {
    int warp = (blockIdx.x * blockDim.x + threadIdx.x) >> 5;
    int lane = threadIdx.x & 31;
    if (warp >= N_NODES) return;
    const float4* H4 = (const float4*)H;

    float selfn = g_dis[warp];
    selfn *= selfn;
    float4 v = H4[(size_t)warp * 32 + lane];
    float4 acc = make_float4(v.x * selfn, v.y * selfn, v.z * selfn, v.w * selfn);

    int s = g_rowptr[warp];
    int e = s + g_cnt[warp];
    for (int p = s; p < e; p++) {
        int src = __ldg(&g_col[p]);
        float w = __ldg(&g_val[p]);
        float4 h = __ldg(&H4[(size_t)src * 32 + lane]);
        acc.x += h.x * w; acc.y += h.y * w;
        acc.z += h.z * w; acc.w += h.w * w;
    }
    ((float4*)out)[(size_t)warp * 32 + lane] = acc;
}

// ---------------- L4 re-association: proj = h3 @ W45 (N x 3), THEN aggregate at D=3 ----------------
__global__ void k_proj(const float* __restrict__ H) {
    int warp = (blockIdx.x * blockDim.x + threadIdx.x) >> 5;
    int lane = threadIdx.x & 31;
    if (warp >= N_NODES) return;
    const float4* H4 = (const float4*)H;

    float s0 = 0.f, s1 = 0.f, s2 = 0.f;
#pragma unroll
    for (int v = 0; v < 2; v++) {
        float4 h = H4[(size_t)warp * 64 + lane + v * 32];
        float a[4] = {h.x, h.y, h.z, h.w};
#pragma unroll
        for (int j = 0; j < 4; j++) {
            int col = 4 * lane + 128 * v + j;
            s0 += a[j] * g_W45[col * 3 + 0];
            s1 += a[j] * g_W45[col * 3 + 1];
            s2 += a[j] * g_W45[col * 3 + 2];
        }
    }
#pragma unroll
    for (int off = 16; off; off >>= 1) {
        s0 += __shfl_down_sync(0xffffffffu, s0, off);
        s1 += __shfl_down_sync(0xffffffffu, s1, off);
        s2 += __shfl_down_sync(0xffffffffu, s2, off);
    }
    if (lane == 0) g_proj[warp] = make_float4(s0, s1, s2, 0.f);
}

__global__ void k_agg3(float* __restrict__ out) {
    int v = blockIdx.x * blockDim.x + threadIdx.x;
    if (v >= N_NODES) return;
    float selfn = g_dis[v];
    selfn *= selfn;
    float4 p = g_proj[v];
    float a0 = p.x * selfn, a1 = p.y * selfn, a2 = p.z * selfn;

    int s = g_rowptr[v];
    int e = s + g_cnt[v];
    for (int q = s; q < e; q++) {
        int src = __ldg(&g_col[q]);
        float w = __ldg(&g_val[q]);
        float4 h = __ldg(&g_proj[src]);
        a0 += h.x * w; a1 += h.y * w; a2 += h.z * w;
    }
    out[(size_t)v * 3 + 0] = a0 + g_b45[0];
    out[(size_t)v * 3 + 1] = a1 + g_b45[1];
    out[(size_t)v * 3 + 2] = a2 + g_b45[2];
}

// ---------------- launch ----------------
extern "C" void kernel_launch(void* const* d_in, const int* in_sizes, int n_in,
                              void* d_out, int out_size) {
    const float* x    = (const float*)d_in[0];
    const void*  ei   = d_in[1];
    const float* ew   = (const float*)d_in[2];
    const float* W1   = (const float*)d_in[3];
    const float* b1   = (const float*)d_in[4];
    const float* W2   = (const float*)d_in[5];
    const float* b2   = (const float*)d_in[6];
    const float* W3   = (const float*)d_in[7];
    const float* b3   = (const float*)d_in[8];
    const float* W4   = (const float*)d_in[9];
    const float* b4   = (const float*)d_in[10];
    const float* Wout = (const float*)d_in[11];
    const float* bout = (const float*)d_in[12];
    float* out = (float*)d_out;

    float* bufA = nullptr;
    float* bufB = nullptr;
    cudaGetSymbolAddress((void**)&bufA, g_bufA);
    cudaGetSymbolAddress((void**)&bufB, g_bufB);

    const int TB = 256;
    int nodeBlocks = (N_NODES + TB - 1) / TB;
    int edgeBlocks = (N_EDGES + TB - 1) / TB;
    int scanBlocks = (N_NODES + 1023) / 1024;
    int warpNodeBlocks = (N_NODES + 7) / 8;

    k_init<<<nodeBlocks, TB>>>();
    k_detect<<<(N_EDGES + TB - 1) / TB, TB>>>((const long long*)ei);
    k_decdeg<<<edgeBlocks, TB>>>(ei, ew);
    k_dis<<<nodeBlocks, TB>>>();
    k_scan1<<<scanBlocks, 1024>>>();
    k_scan2<<<1, 128>>>(scanBlocks);
    k_addoff<<<nodeBlocks, TB>>>();
    k_build<<<edgeBlocks, TB>>>(ei, ew);
    k_w45<<<1, 768>>>(W4, b4, Wout, bout);

    int gm = (N_NODES + 127) / 128;

    // L1: h1 = relu(agg(x @ W1) + b1)        [aggregate at 64]
    k_gemm<<<dim3(gm, 1), 256>>>(x, W1, nullptr, bufA, 128, 64, 0);
    k_agg64<true, true><<<warpNodeBlocks, 256>>>(bufA, b1, bufB);

    // L2: h2 = relu(agg(h1) @ W2 + b2)       [aggregate at 64]
    k_agg64<false, false><<<warpNodeBlocks, 256>>>(bufB, nullptr, bufA);
    k_gemm<<<dim3(gm, 2), 256>>>(bufA, W2, b2, bufB, 64, 128, 1);

    // L3: h3 = relu(agg(h2) @ W3 + b3)       [aggregate at 128]
    k_agg128<<<warpNodeBlocks, 256>>>(bufB, bufA);
    k_gemm<<<dim3(gm, 4), 256>>>(bufA, W3, b3, bufB, 128, 256, 1);

    // L4 + head, re-associated: out = agg(h3 @ W45) + b45   [project first, aggregate at 3]
    k_proj<<<warpNodeBlocks, 256>>>(bufB);
    k_agg3<<<nodeBlocks, TB>>>(out);

    (void)in_sizes; (void)n_in; (void)out_size;
}

// round 5
// speedup vs baseline: 1.7292x; 1.1275x over previous
#include <cuda_runtime.h>

#define N_NODES 100000
#define N_EDGES 1600000

typedef unsigned long long ull;

// ---------------- scratch (__device__ globals; no allocation allowed) ----------------
__device__ float g_deg[N_NODES];
__device__ float g_dis[N_NODES];
__device__ int   g_cnt[N_NODES];
__device__ int   g_rowptr[N_NODES];
__device__ int   g_fill[N_NODES];
__device__ int   g_col[N_EDGES];
__device__ float g_val[N_EDGES];
__device__ int   g_bsum[128];
__device__ int   g_is64;
__device__ float g_W45[256 * 3];
__device__ float g_b45[3];
__device__ float g_bufA[(size_t)N_NODES * 256];
__device__ float g_bufB[(size_t)N_NODES * 256];
__device__ float4 g_proj[N_NODES];

// ---------------- f32x2 packed helpers ----------------
__device__ __forceinline__ ull bcast2(float x) {
    ull r; asm("mov.b64 %0, {%1, %1};" : "=l"(r) : "f"(x)); return r;
}
__device__ __forceinline__ void fma2(ull& d, ull a, ull b) {
    asm("fma.rn.f32x2 %0, %1, %2, %0;" : "+l"(d) : "l"(a), "l"(b));
}
__device__ __forceinline__ void unpack2(ull v, float& lo, float& hi) {
    asm("mov.b64 {%0, %1}, %2;" : "=f"(lo), "=f"(hi) : "l"(v));
}

// ---------------- setup kernels ----------------
__global__ void k_init() {
    int i = blockIdx.x * blockDim.x + threadIdx.x;
    if (i < N_NODES) { g_deg[i] = 1.0f; g_cnt[i] = 0; }
    if (i == 0) g_is64 = 1;
}

__global__ void k_detect(const long long* __restrict__ ei) {
    int i = blockIdx.x * blockDim.x + threadIdx.x;
    if (i < N_EDGES) {
        unsigned long long v = (unsigned long long)ei[i];
        if (v >= (unsigned long long)N_NODES) g_is64 = 0;
    }
}

__device__ __forceinline__ void decode_edge(const void* eiv, int e, int& s, int& d) {
    if (g_is64) {
        const long long* ei = (const long long*)eiv;
        s = (int)ei[e];
        d = (int)ei[N_EDGES + e];
    } else {
        const int* ei = (const int*)eiv;
        s = ei[e];
        d = ei[N_EDGES + e];
    }
}

__global__ void k_decdeg(const void* __restrict__ eiv, const float* __restrict__ ew) {
    int e = blockIdx.x * blockDim.x + threadIdx.x;
    if (e >= N_EDGES) return;
    int s, d;
    decode_edge(eiv, e, s, d);
    atomicAdd(&g_deg[d], ew[e]);
    atomicAdd(&g_cnt[d], 1);
}

__global__ void k_dis() {
    int i = blockIdx.x * blockDim.x + threadIdx.x;
    if (i < N_NODES) g_dis[i] = rsqrtf(g_deg[i]);
}

__global__ void k_scan1() {
    __shared__ int s[1024];
    int tid = threadIdx.x;
    int i = blockIdx.x * 1024 + tid;
    int v = (i < N_NODES) ? g_cnt[i] : 0;
    s[tid] = v;
    __syncthreads();
    for (int off = 1; off < 1024; off <<= 1) {
        int t = (tid >= off) ? s[tid - off] : 0;
        __syncthreads();
        s[tid] += t;
        __syncthreads();
    }
    if (i < N_NODES) g_rowptr[i] = s[tid] - v;
    if (tid == 1023) g_bsum[blockIdx.x] = s[tid];
}

__global__ void k_scan2(int nb) {
    __shared__ int s[128];
    int tid = threadIdx.x;
    int v = (tid < nb) ? g_bsum[tid] : 0;
    s[tid] = v;
    __syncthreads();
    for (int off = 1; off < 128; off <<= 1) {
        int t = (tid >= off) ? s[tid - off] : 0;
        __syncthreads();
        s[tid] += t;
        __syncthreads();
    }
    if (tid < nb) g_bsum[tid] = s[tid] - v;
}

__global__ void k_addoff() {
    int i = blockIdx.x * blockDim.x + threadIdx.x;
    if (i < N_NODES) {
        int r = g_rowptr[i] + g_bsum[i >> 10];
        g_rowptr[i] = r;
        g_fill[i] = r;
    }
}

__global__ void k_build(const void* __restrict__ eiv, const float* __restrict__ ew) {
    int e = blockIdx.x * blockDim.x + threadIdx.x;
    if (e >= N_EDGES) return;
    int s, d;
    decode_edge(eiv, e, s, d);
    float nm = g_dis[s] * ew[e] * g_dis[d];
    int p = atomicAdd(&g_fill[d], 1);
    g_col[p] = s;
    g_val[p] = nm;
}

__global__ void k_w45(const float* __restrict__ W4, const float* __restrict__ b4,
                      const float* __restrict__ Wout, const float* __restrict__ bout) {
    int t = blockIdx.x * blockDim.x + threadIdx.x;
    if (t < 256 * 3) {
        int k = t / 3, c = t % 3;
        float s = 0.f;
        for (int j = 0; j < 256; j++) s += W4[k * 256 + j] * Wout[j * 3 + c];
        g_W45[t] = s;
    }
    if (t < 3) {
        float s = bout[t];
        for (int j = 0; j < 256; j++) s += b4[j] * Wout[j * 3 + t];
        g_b45[t] = s;
    }
}

// ---------------- dense GEMM via f32x2, double-buffered smem ----------------
// tile 128(M) x 64(N), BK=16, 256 threads, 8x4 microtile
__global__ void k_gemm(const float* __restrict__ A, const float* __restrict__ W,
                       const float* __restrict__ bias, float* __restrict__ C,
                       int din, int dout, int relu) {
    __shared__ float As[2][16][132];
    __shared__ float Bs[2][16][64];
    int tid = threadIdx.x;
    int row0 = blockIdx.x * 128;
    int col0 = blockIdx.y * 64;
    int tx = tid & 15;
    int ty = tid >> 4;

    // load indices (fixed per thread)
    int ar0 = tid >> 2, ac0 = (tid & 3) * 4;            // A slot 0: row ar0, k col ac0..+3
    int ar1 = (tid + 256) >> 2, ac1 = ac0;              // A slot 1
    int br = tid >> 4, bc = (tid & 15) * 4;             // B: k row br, col bc..+3

    ull acc[8][2];
#pragma unroll
    for (int i = 0; i < 8; i++) { acc[i][0] = 0ull; acc[i][1] = 0ull; }

    int nk = din >> 4;

    // prologue: load tile 0 into buffer 0
    {
        float4 v0 = make_float4(0.f, 0.f, 0.f, 0.f), v1 = v0;
        if (row0 + ar0 < N_NODES) v0 = *(const float4*)&A[(size_t)(row0 + ar0) * din + ac0];
        if (row0 + ar1 < N_NODES) v1 = *(const float4*)&A[(size_t)(row0 + ar1) * din + ac1];
        float4 vb = *(const float4*)&W[(size_t)br * dout + col0 + bc];
        As[0][ac0 + 0][ar0] = v0.x; As[0][ac0 + 1][ar0] = v0.y;
        As[0][ac0 + 2][ar0] = v0.z; As[0][ac0 + 3][ar0] = v0.w;
        As[0][ac1 + 0][ar1] = v1.x; As[0][ac1 + 1][ar1] = v1.y;
        As[0][ac1 + 2][ar1] = v1.z; As[0][ac1 + 3][ar1] = v1.w;
        *(float4*)&Bs[0][br][bc] = vb;
    }
    __syncthreads();

    for (int kt = 0; kt < nk; kt++) {
        int cur = kt & 1;
        // prefetch next tile into registers
        float4 p0, p1, pb;
        bool more = (kt + 1 < nk);
        if (more) {
            int k0 = (kt + 1) << 4;
            p0 = make_float4(0.f, 0.f, 0.f, 0.f); p1 = p0;
            if (row0 + ar0 < N_NODES) p0 = *(const float4*)&A[(size_t)(row0 + ar0) * din + k0 + ac0];
            if (row0 + ar1 < N_NODES) p1 = *(const float4*)&A[(size_t)(row0 + ar1) * din + k0 + ac1];
            pb = *(const float4*)&W[(size_t)(k0 + br) * dout + col0 + bc];
        }
        // compute on current buffer
#pragma unroll
        for (int k = 0; k < 16; k++) {
            float4 a0 = *(const float4*)&As[cur][k][ty * 8];
            float4 a1 = *(const float4*)&As[cur][k][ty * 8 + 4];
            const ull* bp = (const ull*)&Bs[cur][k][tx * 4];
            ull b0 = bp[0], b1 = bp[1];
            float am[8] = {a0.x, a0.y, a0.z, a0.w, a1.x, a1.y, a1.z, a1.w};
#pragma unroll
            for (int i = 0; i < 8; i++) {
                ull ab = bcast2(am[i]);
                fma2(acc[i][0], ab, b0);
                fma2(acc[i][1], ab, b1);
            }
        }
        if (more) {
            int nxt = cur ^ 1;
            As[nxt][ac0 + 0][ar0] = p0.x; As[nxt][ac0 + 1][ar0] = p0.y;
            As[nxt][ac0 + 2][ar0] = p0.z; As[nxt][ac0 + 3][ar0] = p0.w;
            As[nxt][ac1 + 0][ar1] = p1.x; As[nxt][ac1 + 1][ar1] = p1.y;
            As[nxt][ac1 + 2][ar1] = p1.z; As[nxt][ac1 + 3][ar1] = p1.w;
            *(float4*)&Bs[nxt][br][bc] = pb;
            __syncthreads();
        }
    }

#pragma unroll
    for (int i = 0; i < 8; i++) {
        int r = row0 + ty * 8 + i;
        if (r >= N_NODES) continue;
        float4 v;
        unpack2(acc[i][0], v.x, v.y);
        unpack2(acc[i][1], v.z, v.w);
        int c = col0 + tx * 4;
        if (bias) {
            v.x += bias[c];
            v.y += bias[c + 1];
            v.z += bias[c + 2];
            v.w += bias[c + 3];
        }
        if (relu) {
            v.x = fmaxf(v.x, 0.f); v.y = fmaxf(v.y, 0.f);
            v.z = fmaxf(v.z, 0.f); v.w = fmaxf(v.w, 0.f);
        }
        *(float4*)&C[(size_t)r * dout + c] = v;
    }
}

// ---------------- aggregation D=64: 2 edges per warp (half-warp each), float4 ----------------
template <bool BIAS, bool RELU>
__global__ void k_agg64(const float* __restrict__ H, const float* __restrict__ bias,
                        float* __restrict__ out) {
    int warp = (blockIdx.x * blockDim.x + threadIdx.x) >> 5;
    int lane = threadIdx.x & 31;
    if (warp >= N_NODES) return;
    int half = lane >> 4, hl = lane & 15;
    const float4* H4 = (const float4*)H;

    float4 acc = make_float4(0.f, 0.f, 0.f, 0.f);
    if (half == 0) {
        float selfn = g_dis[warp];
        selfn *= selfn;
        float4 v = H4[(size_t)warp * 16 + hl];
        acc.x = v.x * selfn; acc.y = v.y * selfn;
        acc.z = v.z * selfn; acc.w = v.w * selfn;
    }
    int s = g_rowptr[warp];
    int e = s + g_cnt[warp];
#pragma unroll 2
    for (int p = s + half; p < e; p += 2) {
        int src = __ldg(&g_col[p]);
        float w = __ldg(&g_val[p]);
        float4 v = __ldg(&H4[(size_t)src * 16 + hl]);
        acc.x += v.x * w; acc.y += v.y * w;
        acc.z += v.z * w; acc.w += v.w * w;
    }
    __syncwarp();
    acc.x += __shfl_xor_sync(0xffffffffu, acc.x, 16);
    acc.y += __shfl_xor_sync(0xffffffffu, acc.y, 16);
    acc.z += __shfl_xor_sync(0xffffffffu, acc.z, 16);
    acc.w += __shfl_xor_sync(0xffffffffu, acc.w, 16);
    if (half == 0) {
        if (BIAS) {
            float4 b = ((const float4*)bias)[hl];
            acc.x += b.x; acc.y += b.y; acc.z += b.z; acc.w += b.w;
        }
        if (RELU) {
            acc.x = fmaxf(acc.x, 0.f); acc.y = fmaxf(acc.y, 0.f);
            acc.z = fmaxf(acc.z, 0.f); acc.w = fmaxf(acc.w, 0.f);
        }
        ((float4*)out)[(size_t)warp * 16 + hl] = acc;
    }
}

// ---------------- aggregation D=128: 1 float4 per lane ----------------
__global__ void k_agg128(const float* __restrict__ H, float* __restrict__ out) {
    int warp = (blockIdx.x * blockDim.x + threadIdx.x) >> 5;
    int lane = threadIdx.x & 31;
    if (warp >= N_NODES) return;
    const float4* H4 = (const float4*)H;

    float selfn = g_dis[warp];
    selfn *= selfn;
    float4 v = H4[(size_t)warp * 32 + lane];
    float4 acc = make_float4(v.x * selfn, v.y * selfn, v.z * selfn, v.w * selfn);

    int s = g_rowptr[warp];
    int e = s + g_cnt[warp];
#pragma unroll 2
    for (int p = s; p < e; p++) {
        int src = __ldg(&g_col[p]);
        float w = __ldg(&g_val[p]);
        float4 h = __ldg(&H4[(size_t)src * 32 + lane]);
        acc.x += h.x * w; acc.y += h.y * w;
        acc.z += h.z * w; acc.w += h.w * w;
    }
    ((float4*)out)[(size_t)warp * 32 + lane] = acc;
}

// ---------------- L4 re-association: proj = h3 @ W45 (N x 3), THEN aggregate at D=3 ----------------
__global__ void k_proj(const float* __restrict__ H) {
    int warp = (blockIdx.x * blockDim.x + threadIdx.x) >> 5;
    int lane = threadIdx.x & 31;
    if (warp >= N_NODES) return;
    const float4* H4 = (const float4*)H;

    float s0 = 0.f, s1 = 0.f, s2 = 0.f;
#pragma unroll
    for (int v = 0; v < 2; v++) {
        float4 h = H4[(size_t)warp * 64 + lane + v * 32];
        float a[4] = {h.x, h.y, h.z, h.w};
#pragma unroll
        for (int j = 0; j < 4; j++) {
            int col = 4 * lane + 128 * v + j;
            s0 += a[j] * g_W45[col * 3 + 0];
            s1 += a[j] * g_W45[col * 3 + 1];
            s2 += a[j] * g_W45[col * 3 + 2];
        }
    }
#pragma unroll
    for (int off = 16; off; off >>= 1) {
        s0 += __shfl_down_sync(0xffffffffu, s0, off);
        s1 += __shfl_down_sync(0xffffffffu, s1, off);
        s2 += __shfl_down_sync(0xffffffffu, s2, off);
    }
    if (lane == 0) g_proj[warp] = make_float4(s0, s1, s2, 0.f);
}

__global__ void k_agg3(float* __restrict__ out) {
    int v = blockIdx.x * blockDim.x + threadIdx.x;
    if (v >= N_NODES) return;
    float selfn = g_dis[v];
    selfn *= selfn;
    float4 p = g_proj[v];
    float a0 = p.x * selfn, a1 = p.y * selfn, a2 = p.z * selfn;

    int s = g_rowptr[v];
    int e = s + g_cnt[v];
#pragma unroll 2
    for (int q = s; q < e; q++) {
        int src = __ldg(&g_col[q]);
        float w = __ldg(&g_val[q]);
        float4 h = __ldg(&g_proj[src]);
        a0 += h.x * w; a1 += h.y * w; a2 += h.z * w;
    }
    out[(size_t)v * 3 + 0] = a0 + g_b45[0];
    out[(size_t)v * 3 + 1] = a1 + g_b45[1];
    out[(size_t)v * 3 + 2] = a2 + g_b45[2];
}

// ---------------- launch ----------------
extern "C" void kernel_launch(void* const* d_in, const int* in_sizes, int n_in,
                              void* d_out, int out_size) {
    const float* x    = (const float*)d_in[0];
    const void*  ei   = d_in[1];
    const float* ew   = (const float*)d_in[2];
    const float* W1   = (const float*)d_in[3];
    const float* b1   = (const float*)d_in[4];
    const float* W2   = (const float*)d_in[5];
    const float* b2   = (const float*)d_in[6];
    const float* W3   = (const float*)d_in[7];
    const float* b3   = (const float*)d_in[8];
    const float* W4   = (const float*)d_in[9];
    const float* b4   = (const float*)d_in[10];
    const float* Wout = (const float*)d_in[11];
    const float* bout = (const float*)d_in[12];
    float* out = (float*)d_out;

    float* bufA = nullptr;
    float* bufB = nullptr;
    cudaGetSymbolAddress((void**)&bufA, g_bufA);
    cudaGetSymbolAddress((void**)&bufB, g_bufB);

    // side stream + events, created once on first (non-capture) call
    static cudaStream_t s2 = nullptr;
    static cudaEvent_t evFork = nullptr, evJoin = nullptr;
    if (!s2) {
        cudaStreamCreateWithFlags(&s2, cudaStreamNonBlocking);
        cudaEventCreateWithFlags(&evFork, cudaEventDisableTiming);
        cudaEventCreateWithFlags(&evJoin, cudaEventDisableTiming);
    }

    const int TB = 256;
    int nodeBlocks = (N_NODES + TB - 1) / TB;
    int edgeBlocks = (N_EDGES + TB - 1) / TB;
    int scanBlocks = (N_NODES + 1023) / 1024;
    int warpNodeBlocks = (N_NODES + 7) / 8;
    int gm = (N_NODES + 127) / 128;

    // fork: GEMM1 (x @ W1) and W45 fold are independent of the graph preprocessing
    cudaEventRecord(evFork, 0);
    cudaStreamWaitEvent(s2, evFork, 0);
    k_gemm<<<dim3(gm, 1), 256, 0, s2>>>(x, W1, nullptr, bufA, 128, 64, 0);
    k_w45<<<1, 768, 0, s2>>>(W4, b4, Wout, bout);
    cudaEventRecord(evJoin, s2);

    // main stream: CSR preprocessing
    k_init<<<nodeBlocks, TB>>>();
    k_detect<<<(N_EDGES + TB - 1) / TB, TB>>>((const long long*)ei);
    k_decdeg<<<edgeBlocks, TB>>>(ei, ew);
    k_dis<<<nodeBlocks, TB>>>();
    k_scan1<<<scanBlocks, 1024>>>();
    k_scan2<<<1, 128>>>(scanBlocks);
    k_addoff<<<nodeBlocks, TB>>>();
    k_build<<<edgeBlocks, TB>>>(ei, ew);

    // join: aggregation needs both CSR and GEMM1 output
    cudaStreamWaitEvent(0, evJoin, 0);

    // L1: h1 = relu(agg(x @ W1) + b1)        [aggregate at 64]
    k_agg64<true, true><<<warpNodeBlocks, 256>>>(bufA, b1, bufB);

    // L2: h2 = relu(agg(h1) @ W2 + b2)       [aggregate at 64]
    k_agg64<false, false><<<warpNodeBlocks, 256>>>(bufB, nullptr, bufA);
    k_gemm<<<dim3(gm, 2), 256>>>(bufA, W2, b2, bufB, 64, 128, 1);

    // L3: h3 = relu(agg(h2) @ W3 + b3)       [aggregate at 128]
    k_agg128<<<warpNodeBlocks, 256>>>(bufB, bufA);
    k_gemm<<<dim3(gm, 4), 256>>>(bufA, W3, b3, bufB, 128, 256, 1);

    // L4 + head, re-associated: out = agg(h3 @ W45) + b45   [project first, aggregate at 3]
    k_proj<<<warpNodeBlocks, 256>>>(bufB);
    k_agg3<<<nodeBlocks, TB>>>(out);

    (void)in_sizes; (void)n_in; (void)out_size;
}

// round 6
// speedup vs baseline: 1.8394x; 1.0637x over previous
#include <cuda_runtime.h>
#include <cuda_fp16.h>

#define N_NODES 100000
#define N_EDGES 1600000

typedef unsigned long long ull;

// ---------------- scratch (__device__ globals; no allocation allowed) ----------------
__device__ float g_deg[N_NODES];
__device__ float g_dis[N_NODES];
__device__ int   g_cnt[N_NODES];
__device__ int   g_rowptr[N_NODES];
__device__ int   g_fill[N_NODES];
__device__ int   g_col[N_EDGES];
__device__ float g_val[N_EDGES];
__device__ int   g_bsum[128];
__device__ int   g_is64;
__device__ float g_W45[256 * 3];
__device__ float g_b45[3];
__device__ float g_bufA[(size_t)N_NODES * 256];
__device__ float g_bufB[(size_t)N_NODES * 256];
__device__ __half g_h16A[(size_t)N_NODES * 128];   // gemm1 out (64) / gemm2 out (128)
__device__ __half g_h16B[(size_t)N_NODES * 64];    // L1 agg out (64)
__device__ float4 g_proj[N_NODES];

// ---------------- f32x2 packed helpers ----------------
__device__ __forceinline__ ull bcast2(float x) {
    ull r; asm("mov.b64 %0, {%1, %1};" : "=l"(r) : "f"(x)); return r;
}
__device__ __forceinline__ void fma2(ull& d, ull a, ull b) {
    asm("fma.rn.f32x2 %0, %1, %2, %0;" : "+l"(d) : "l"(a), "l"(b));
}
__device__ __forceinline__ void unpack2(ull v, float& lo, float& hi) {
    asm("mov.b64 {%0, %1}, %2;" : "=f"(lo), "=f"(hi) : "l"(v));
}

// ---------------- setup kernels ----------------
__global__ void k_init() {
    int i = blockIdx.x * blockDim.x + threadIdx.x;
    if (i < N_NODES) { g_deg[i] = 1.0f; g_cnt[i] = 0; }
    if (i == 0) g_is64 = 1;
}

#define DETECT_WORDS (1 << 18)
__global__ void k_detect(const long long* __restrict__ ei) {
    int i = blockIdx.x * blockDim.x + threadIdx.x;
    if (i < DETECT_WORDS) {
        unsigned long long v = (unsigned long long)ei[i];
        if (v >= (unsigned long long)N_NODES) g_is64 = 0;
    }
}

__device__ __forceinline__ void decode_edge(const void* eiv, int e, int& s, int& d) {
    if (g_is64) {
        const long long* ei = (const long long*)eiv;
        s = (int)ei[e];
        d = (int)ei[N_EDGES + e];
    } else {
        const int* ei = (const int*)eiv;
        s = ei[e];
        d = ei[N_EDGES + e];
    }
}

__global__ void k_decdeg(const void* __restrict__ eiv, const float* __restrict__ ew) {
    int e = blockIdx.x * blockDim.x + threadIdx.x;
    if (e >= N_EDGES) return;
    int s, d;
    decode_edge(eiv, e, s, d);
    atomicAdd(&g_deg[d], ew[e]);
    atomicAdd(&g_cnt[d], 1);
}

__global__ void k_dis() {
    int i = blockIdx.x * blockDim.x + threadIdx.x;
    if (i < N_NODES) g_dis[i] = rsqrtf(g_deg[i]);
}

__global__ void k_scan1() {
    __shared__ int s[1024];
    int tid = threadIdx.x;
    int i = blockIdx.x * 1024 + tid;
    int v = (i < N_NODES) ? g_cnt[i] : 0;
    s[tid] = v;
    __syncthreads();
    for (int off = 1; off < 1024; off <<= 1) {
        int t = (tid >= off) ? s[tid - off] : 0;
        __syncthreads();
        s[tid] += t;
        __syncthreads();
    }
    if (i < N_NODES) g_rowptr[i] = s[tid] - v;
    if (tid == 1023) g_bsum[blockIdx.x] = s[tid];
}

__global__ void k_scan2(int nb) {
    __shared__ int s[128];
    int tid = threadIdx.x;
    int v = (tid < nb) ? g_bsum[tid] : 0;
    s[tid] = v;
    __syncthreads();
    for (int off = 1; off < 128; off <<= 1) {
        int t = (tid >= off) ? s[tid - off] : 0;
        __syncthreads();
        s[tid] += t;
        __syncthreads();
    }
    if (tid < nb) g_bsum[tid] = s[tid] - v;
}

__global__ void k_addoff() {
    int i = blockIdx.x * blockDim.x + threadIdx.x;
    if (i < N_NODES) {
        int r = g_rowptr[i] + g_bsum[i >> 10];
        g_rowptr[i] = r;
        g_fill[i] = r;
    }
}

__global__ void k_build(const void* __restrict__ eiv, const float* __restrict__ ew) {
    int e = blockIdx.x * blockDim.x + threadIdx.x;
    if (e >= N_EDGES) return;
    int s, d;
    decode_edge(eiv, e, s, d);
    float nm = g_dis[s] * ew[e] * g_dis[d];
    int p = atomicAdd(&g_fill[d], 1);
    g_col[p] = s;
    g_val[p] = nm;
}

__global__ void k_w45(const float* __restrict__ W4, const float* __restrict__ b4,
                      const float* __restrict__ Wout, const float* __restrict__ bout) {
    int t = blockIdx.x * blockDim.x + threadIdx.x;
    if (t < 256 * 3) {
        int k = t / 3, c = t % 3;
        float s = 0.f;
        for (int j = 0; j < 256; j++) s += W4[k * 256 + j] * Wout[j * 3 + c];
        g_W45[t] = s;
    }
    if (t < 3) {
        float s = bout[t];
        for (int j = 0; j < 256; j++) s += b4[j] * Wout[j * 3 + t];
        g_b45[t] = s;
    }
}

// ---------------- dense GEMM via f32x2, double-buffered; optional fp16 store ----------------
// tile 128(M) x 64(N), BK=16, 256 threads, 8x4 microtile
template <bool OUT16>
__global__ void k_gemm(const float* __restrict__ A, const float* __restrict__ W,
                       const float* __restrict__ bias, void* __restrict__ Cv,
                       int din, int dout, int relu) {
    __shared__ float As[2][16][132];
    __shared__ float Bs[2][16][64];
    int tid = threadIdx.x;
    int row0 = blockIdx.x * 128;
    int col0 = blockIdx.y * 64;
    int tx = tid & 15;
    int ty = tid >> 4;

    int ar0 = tid >> 2, ac0 = (tid & 3) * 4;
    int ar1 = (tid + 256) >> 2, ac1 = ac0;
    int br = tid >> 4, bc = (tid & 15) * 4;

    ull acc[8][2];
#pragma unroll
    for (int i = 0; i < 8; i++) { acc[i][0] = 0ull; acc[i][1] = 0ull; }

    int nk = din >> 4;

    {
        float4 v0 = make_float4(0.f, 0.f, 0.f, 0.f), v1 = v0;
        if (row0 + ar0 < N_NODES) v0 = *(const float4*)&A[(size_t)(row0 + ar0) * din + ac0];
        if (row0 + ar1 < N_NODES) v1 = *(const float4*)&A[(size_t)(row0 + ar1) * din + ac1];
        float4 vb = *(const float4*)&W[(size_t)br * dout + col0 + bc];
        As[0][ac0 + 0][ar0] = v0.x; As[0][ac0 + 1][ar0] = v0.y;
        As[0][ac0 + 2][ar0] = v0.z; As[0][ac0 + 3][ar0] = v0.w;
        As[0][ac1 + 0][ar1] = v1.x; As[0][ac1 + 1][ar1] = v1.y;
        As[0][ac1 + 2][ar1] = v1.z; As[0][ac1 + 3][ar1] = v1.w;
        *(float4*)&Bs[0][br][bc] = vb;
    }
    __syncthreads();

    for (int kt = 0; kt < nk; kt++) {
        int cur = kt & 1;
        float4 p0, p1, pb;
        bool more = (kt + 1 < nk);
        if (more) {
            int k0 = (kt + 1) << 4;
            p0 = make_float4(0.f, 0.f, 0.f, 0.f); p1 = p0;
            if (row0 + ar0 < N_NODES) p0 = *(const float4*)&A[(size_t)(row0 + ar0) * din + k0 + ac0];
            if (row0 + ar1 < N_NODES) p1 = *(const float4*)&A[(size_t)(row0 + ar1) * din + k0 + ac1];
            pb = *(const float4*)&W[(size_t)(k0 + br) * dout + col0 + bc];
        }
#pragma unroll
        for (int k = 0; k < 16; k++) {
            float4 a0 = *(const float4*)&As[cur][k][ty * 8];
            float4 a1 = *(const float4*)&As[cur][k][ty * 8 + 4];
            const ull* bp = (const ull*)&Bs[cur][k][tx * 4];
            ull b0 = bp[0], b1 = bp[1];
            float am[8] = {a0.x, a0.y, a0.z, a0.w, a1.x, a1.y, a1.z, a1.w};
#pragma unroll
            for (int i = 0; i < 8; i++) {
                ull ab = bcast2(am[i]);
                fma2(acc[i][0], ab, b0);
                fma2(acc[i][1], ab, b1);
            }
        }
        if (more) {
            int nxt = cur ^ 1;
            As[nxt][ac0 + 0][ar0] = p0.x; As[nxt][ac0 + 1][ar0] = p0.y;
            As[nxt][ac0 + 2][ar0] = p0.z; As[nxt][ac0 + 3][ar0] = p0.w;
            As[nxt][ac1 + 0][ar1] = p1.x; As[nxt][ac1 + 1][ar1] = p1.y;
            As[nxt][ac1 + 2][ar1] = p1.z; As[nxt][ac1 + 3][ar1] = p1.w;
            *(float4*)&Bs[nxt][br][bc] = pb;
            __syncthreads();
        }
    }

#pragma unroll
    for (int i = 0; i < 8; i++) {
        int r = row0 + ty * 8 + i;
        if (r >= N_NODES) continue;
        float4 v;
        unpack2(acc[i][0], v.x, v.y);
        unpack2(acc[i][1], v.z, v.w);
        int c = col0 + tx * 4;
        if (bias) {
            v.x += bias[c];
            v.y += bias[c + 1];
            v.z += bias[c + 2];
            v.w += bias[c + 3];
        }
        if (relu) {
            v.x = fmaxf(v.x, 0.f); v.y = fmaxf(v.y, 0.f);
            v.z = fmaxf(v.z, 0.f); v.w = fmaxf(v.w, 0.f);
        }
        if (OUT16) {
            __half2 h0 = __floats2half2_rn(v.x, v.y);
            __half2 h1 = __floats2half2_rn(v.z, v.w);
            uint2 pk;
            pk.x = *(unsigned*)&h0;
            pk.y = *(unsigned*)&h1;
            *(uint2*)((__half*)Cv + (size_t)r * dout + c) = pk;
        } else {
            *(float4*)((float*)Cv + (size_t)r * dout + c) = v;
        }
    }
}

// ---------------- aggregation D=64 fp16-in: 4 edges per warp (8 lanes x 16B each) ----------------
template <bool BIAS, bool RELU, bool OUT16>
__global__ void k_agg64(const __half* __restrict__ H, const float* __restrict__ bias,
                        void* __restrict__ out) {
    int warp = (blockIdx.x * blockDim.x + threadIdx.x) >> 5;
    int lane = threadIdx.x & 31;
    if (warp >= N_NODES) return;
    int grp = lane >> 3, gl = lane & 7;
    const uint4* H4 = (const uint4*)H;   // row = 8 x uint4

    float a[8];
#pragma unroll
    for (int j = 0; j < 8; j++) a[j] = 0.f;

    if (grp == 0) {
        float selfn = g_dis[warp];
        selfn *= selfn;
        uint4 v = H4[(size_t)warp * 8 + gl];
        const __half2* h2 = (const __half2*)&v;
#pragma unroll
        for (int j = 0; j < 4; j++) {
            float2 f = __half22float2(h2[j]);
            a[2 * j] = f.x * selfn;
            a[2 * j + 1] = f.y * selfn;
        }
    }

    int s = g_rowptr[warp];
    int e = s + g_cnt[warp];
    for (int p = s + grp; p < e; p += 4) {
        int src = __ldg(&g_col[p]);
        float w = __ldg(&g_val[p]);
        uint4 v = __ldg(&H4[(size_t)src * 8 + gl]);
        const __half2* h2 = (const __half2*)&v;
#pragma unroll
        for (int j = 0; j < 4; j++) {
            float2 f = __half22float2(h2[j]);
            a[2 * j] += f.x * w;
            a[2 * j + 1] += f.y * w;
        }
    }
    __syncwarp();
#pragma unroll
    for (int j = 0; j < 8; j++) {
        a[j] += __shfl_xor_sync(0xffffffffu, a[j], 8);
        a[j] += __shfl_xor_sync(0xffffffffu, a[j], 16);
    }
    if (grp == 0) {
#pragma unroll
        for (int j = 0; j < 8; j++) {
            if (BIAS) a[j] += bias[gl * 8 + j];
            if (RELU) a[j] = fmaxf(a[j], 0.f);
        }
        if (OUT16) {
            uint4 pk;
            __half2 h0 = __floats2half2_rn(a[0], a[1]);
            __half2 h1 = __floats2half2_rn(a[2], a[3]);
            __half2 h2o = __floats2half2_rn(a[4], a[5]);
            __half2 h3 = __floats2half2_rn(a[6], a[7]);
            pk.x = *(unsigned*)&h0; pk.y = *(unsigned*)&h1;
            pk.z = *(unsigned*)&h2o; pk.w = *(unsigned*)&h3;
            ((uint4*)out)[(size_t)warp * 8 + gl] = pk;
        } else {
            float* o = (float*)out + (size_t)warp * 64 + gl * 8;
            *(float4*)&o[0] = make_float4(a[0], a[1], a[2], a[3]);
            *(float4*)&o[4] = make_float4(a[4], a[5], a[6], a[7]);
        }
    }
}

// ---------------- aggregation D=128 fp16-in: 2 edges per warp (16 lanes x 16B), fp32 out ----------------
__global__ void k_agg128(const __half* __restrict__ H, float* __restrict__ out) {
    int warp = (blockIdx.x * blockDim.x + threadIdx.x) >> 5;
    int lane = threadIdx.x & 31;
    if (warp >= N_NODES) return;
    int half = lane >> 4, hl = lane & 15;
    const uint4* H4 = (const uint4*)H;   // row = 16 x uint4

    float a[8];
#pragma unroll
    for (int j = 0; j < 8; j++) a[j] = 0.f;

    if (half == 0) {
        float selfn = g_dis[warp];
        selfn *= selfn;
        uint4 v = H4[(size_t)warp * 16 + hl];
        const __half2* h2 = (const __half2*)&v;
#pragma unroll
        for (int j = 0; j < 4; j++) {
            float2 f = __half22float2(h2[j]);
            a[2 * j] = f.x * selfn;
            a[2 * j + 1] = f.y * selfn;
        }
    }

    int s = g_rowptr[warp];
    int e = s + g_cnt[warp];
    for (int p = s + half; p < e; p += 2) {
        int src = __ldg(&g_col[p]);
        float w = __ldg(&g_val[p]);
        uint4 v = __ldg(&H4[(size_t)src * 16 + hl]);
        const __half2* h2 = (const __half2*)&v;
#pragma unroll
        for (int j = 0; j < 4; j++) {
            float2 f = __half22float2(h2[j]);
            a[2 * j] += f.x * w;
            a[2 * j + 1] += f.y * w;
        }
    }
    __syncwarp();
#pragma unroll
    for (int j = 0; j < 8; j++)
        a[j] += __shfl_xor_sync(0xffffffffu, a[j], 16);
    if (half == 0) {
        float* o = out + (size_t)warp * 128 + hl * 8;
        *(float4*)&o[0] = make_float4(a[0], a[1], a[2], a[3]);
        *(float4*)&o[4] = make_float4(a[4], a[5], a[6], a[7]);
    }
}

// ---------------- L4 re-association: proj = h3 @ W45 (N x 3), THEN aggregate at D=3 ----------------
__global__ void k_proj(const float* __restrict__ H) {
    int warp = (blockIdx.x * blockDim.x + threadIdx.x) >> 5;
    int lane = threadIdx.x & 31;
    if (warp >= N_NODES) return;
    const float4* H4 = (const float4*)H;

    float s0 = 0.f, s1 = 0.f, s2 = 0.f;
#pragma unroll
    for (int v = 0; v < 2; v++) {
        float4 h = H4[(size_t)warp * 64 + lane + v * 32];
        float a[4] = {h.x, h.y, h.z, h.w};
#pragma unroll
        for (int j = 0; j < 4; j++) {
            int col = 4 * lane + 128 * v + j;
            s0 += a[j] * g_W45[col * 3 + 0];
            s1 += a[j] * g_W45[col * 3 + 1];
            s2 += a[j] * g_W45[col * 3 + 2];
        }
    }
#pragma unroll
    for (int off = 16; off; off >>= 1) {
        s0 += __shfl_down_sync(0xffffffffu, s0, off);
        s1 += __shfl_down_sync(0xffffffffu, s1, off);
        s2 += __shfl_down_sync(0xffffffffu, s2, off);
    }
    if (lane == 0) g_proj[warp] = make_float4(s0, s1, s2, 0.f);
}

__global__ void k_agg3(float* __restrict__ out) {
    int v = blockIdx.x * blockDim.x + threadIdx.x;
    if (v >= N_NODES) return;
    float selfn = g_dis[v];
    selfn *= selfn;
    float4 p = g_proj[v];
    float a0 = p.x * selfn, a1 = p.y * selfn, a2 = p.z * selfn;

    int s = g_rowptr[v];
    int e = s + g_cnt[v];
#pragma unroll 2
    for (int q = s; q < e; q++) {
        int src = __ldg(&g_col[q]);
        float w = __ldg(&g_val[q]);
        float4 h = __ldg(&g_proj[src]);
        a0 += h.x * w; a1 += h.y * w; a2 += h.z * w;
    }
    out[(size_t)v * 3 + 0] = a0 + g_b45[0];
    out[(size_t)v * 3 + 1] = a1 + g_b45[1];
    out[(size_t)v * 3 + 2] = a2 + g_b45[2];
}

// ---------------- launch ----------------
extern "C" void kernel_launch(void* const* d_in, const int* in_sizes, int n_in,
                              void* d_out, int out_size) {
    const float* x    = (const float*)d_in[0];
    const void*  ei   = d_in[1];
    const float* ew   = (const float*)d_in[2];
    const float* W1   = (const float*)d_in[3];
    const float* b1   = (const float*)d_in[4];
    const float* W2   = (const float*)d_in[5];
    const float* b2   = (const float*)d_in[6];
    const float* W3   = (const float*)d_in[7];
    const float* b3   = (const float*)d_in[8];
    const float* W4   = (const float*)d_in[9];
    const float* b4   = (const float*)d_in[10];
    const float* Wout = (const float*)d_in[11];
    const float* bout = (const float*)d_in[12];
    float* out = (float*)d_out;

    float* bufA = nullptr;
    float* bufB = nullptr;
    __half* h16A = nullptr;
    __half* h16B = nullptr;
    cudaGetSymbolAddress((void**)&bufA, g_bufA);
    cudaGetSymbolAddress((void**)&bufB, g_bufB);
    cudaGetSymbolAddress((void**)&h16A, g_h16A);
    cudaGetSymbolAddress((void**)&h16B, g_h16B);

    static cudaStream_t s2 = nullptr;
    static cudaEvent_t evFork = nullptr, evJoin = nullptr;
    if (!s2) {
        cudaStreamCreateWithFlags(&s2, cudaStreamNonBlocking);
        cudaEventCreateWithFlags(&evFork, cudaEventDisableTiming);
        cudaEventCreateWithFlags(&evJoin, cudaEventDisableTiming);
    }

    const int TB = 256;
    int nodeBlocks = (N_NODES + TB - 1) / TB;
    int edgeBlocks = (N_EDGES + TB - 1) / TB;
    int scanBlocks = (N_NODES + 1023) / 1024;
    int warpNodeBlocks = (N_NODES + 7) / 8;
    int gm = (N_NODES + 127) / 128;

    // fork: GEMM1 (x @ W1) and W45 fold are independent of the graph preprocessing.
    // NOTE: k_detect must complete before decode-dependent kernels only (main stream).
    cudaEventRecord(evFork, 0);
    cudaStreamWaitEvent(s2, evFork, 0);
    k_gemm<true><<<dim3(gm, 1), 256, 0, s2>>>(x, W1, nullptr, h16A, 128, 64, 0);
    k_w45<<<1, 768, 0, s2>>>(W4, b4, Wout, bout);
    cudaEventRecord(evJoin, s2);

    // main stream: CSR preprocessing
    k_init<<<nodeBlocks, TB>>>();
    k_detect<<<(DETECT_WORDS + TB - 1) / TB, TB>>>((const long long*)ei);
    k_decdeg<<<edgeBlocks, TB>>>(ei, ew);
    k_dis<<<nodeBlocks, TB>>>();
    k_scan1<<<scanBlocks, 1024>>>();
    k_scan2<<<1, 128>>>(scanBlocks);
    k_addoff<<<nodeBlocks, TB>>>();
    k_build<<<edgeBlocks, TB>>>(ei, ew);

    cudaStreamWaitEvent(0, evJoin, 0);

    // L1: h1 = relu(agg(x @ W1) + b1)        [aggregate at 64, fp16 gathers]
    k_agg64<true, true, true><<<warpNodeBlocks, 256>>>(h16A, b1, h16B);

    // L2: h2 = relu(agg(h1) @ W2 + b2)       [aggregate at 64, fp16 gathers]
    k_agg64<false, false, false><<<warpNodeBlocks, 256>>>(h16B, nullptr, bufA);
    k_gemm<true><<<dim3(gm, 2), 256>>>(bufA, W2, b2, h16A, 64, 128, 1);

    // L3: h3 = relu(agg(h2) @ W3 + b3)       [aggregate at 128, fp16 gathers]
    k_agg128<<<warpNodeBlocks, 256>>>(h16A, bufA);
    k_gemm<false><<<dim3(gm, 4), 256>>>(bufA, W3, b3, bufB, 128, 256, 1);

    // L4 + head, re-associated: out = agg(h3 @ W45) + b45   [project first, aggregate at 3]
    k_proj<<<warpNodeBlocks, 256>>>(bufB);
    k_agg3<<<nodeBlocks, TB>>>(out);

    (void)in_sizes; (void)n_in; (void)out_size;
}

// round 7
// speedup vs baseline: 2.1922x; 1.1918x over previous
#include <cuda_runtime.h>
#include <cuda_fp16.h>
#include <mma.h>

using namespace nvcuda;

#define N_NODES 100000
#define N_EDGES 1600000

typedef unsigned long long ull;

// ---------------- scratch (__device__ globals; no allocation allowed) ----------------
__device__ float g_deg[N_NODES];
__device__ float g_dis[N_NODES];
__device__ int   g_cnt[N_NODES];
__device__ int   g_rowptr[N_NODES];
__device__ int   g_fill[N_NODES];
__device__ int   g_col[N_EDGES];
__device__ float g_val[N_EDGES];
__device__ int   g_bsum[128];
__device__ int   g_is64;
__device__ float g_W45[256 * 3];
__device__ float g_b45[3];
__device__ __half g_hx[(size_t)N_NODES * 128];   // x in fp16
__device__ __half g_hA[(size_t)N_NODES * 256];   // ping
__device__ __half g_hB[(size_t)N_NODES * 256];   // pong
__device__ __half g_hW1[128 * 64];
__device__ __half g_hW2[64 * 128];
__device__ __half g_hW3[128 * 256];
__device__ float4 g_proj[N_NODES];

// ---------------- setup kernels ----------------
__global__ void k_init() {
    int i = blockIdx.x * blockDim.x + threadIdx.x;
    if (i < N_NODES) { g_deg[i] = 1.0f; g_cnt[i] = 0; }
    if (i == 0) g_is64 = 1;
}

#define DETECT_WORDS (1 << 18)
__global__ void k_detect(const long long* __restrict__ ei) {
    int i = blockIdx.x * blockDim.x + threadIdx.x;
    if (i < DETECT_WORDS) {
        unsigned long long v = (unsigned long long)ei[i];
        if (v >= (unsigned long long)N_NODES) g_is64 = 0;
    }
}

__device__ __forceinline__ void decode_edge(const void* eiv, int e, int& s, int& d) {
    if (g_is64) {
        const long long* ei = (const long long*)eiv;
        s = (int)ei[e];
        d = (int)ei[N_EDGES + e];
    } else {
        const int* ei = (const int*)eiv;
        s = ei[e];
        d = ei[N_EDGES + e];
    }
}

__global__ void k_decdeg(const void* __restrict__ eiv, const float* __restrict__ ew) {
    int e = blockIdx.x * blockDim.x + threadIdx.x;
    if (e >= N_EDGES) return;
    int s, d;
    decode_edge(eiv, e, s, d);
    atomicAdd(&g_deg[d], ew[e]);
    atomicAdd(&g_cnt[d], 1);
}

__global__ void k_dis() {
    int i = blockIdx.x * blockDim.x + threadIdx.x;
    if (i < N_NODES) g_dis[i] = rsqrtf(g_deg[i]);
}

__global__ void k_scan1() {
    __shared__ int s[1024];
    int tid = threadIdx.x;
    int i = blockIdx.x * 1024 + tid;
    int v = (i < N_NODES) ? g_cnt[i] : 0;
    s[tid] = v;
    __syncthreads();
    for (int off = 1; off < 1024; off <<= 1) {
        int t = (tid >= off) ? s[tid - off] : 0;
        __syncthreads();
        s[tid] += t;
        __syncthreads();
    }
    if (i < N_NODES) g_rowptr[i] = s[tid] - v;
    if (tid == 1023) g_bsum[blockIdx.x] = s[tid];
}

__global__ void k_scan2(int nb) {
    __shared__ int s[128];
    int tid = threadIdx.x;
    int v = (tid < nb) ? g_bsum[tid] : 0;
    s[tid] = v;
    __syncthreads();
    for (int off = 1; off < 128; off <<= 1) {
        int t = (tid >= off) ? s[tid - off] : 0;
        __syncthreads();
        s[tid] += t;
        __syncthreads();
    }
    if (tid < nb) g_bsum[tid] = s[tid] - v;
}

__global__ void k_addoff() {
    int i = blockIdx.x * blockDim.x + threadIdx.x;
    if (i < N_NODES) {
        int r = g_rowptr[i] + g_bsum[i >> 10];
        g_rowptr[i] = r;
        g_fill[i] = r;
    }
}

__global__ void k_build(const void* __restrict__ eiv, const float* __restrict__ ew) {
    int e = blockIdx.x * blockDim.x + threadIdx.x;
    if (e >= N_EDGES) return;
    int s, d;
    decode_edge(eiv, e, s, d);
    float nm = g_dis[s] * ew[e] * g_dis[d];
    int p = atomicAdd(&g_fill[d], 1);
    g_col[p] = s;
    g_val[p] = nm;
}

__global__ void k_w45(const float* __restrict__ W4, const float* __restrict__ b4,
                      const float* __restrict__ Wout, const float* __restrict__ bout) {
    int t = blockIdx.x * blockDim.x + threadIdx.x;
    if (t < 256 * 3) {
        int k = t / 3, c = t % 3;
        float s = 0.f;
        for (int j = 0; j < 256; j++) s += W4[k * 256 + j] * Wout[j * 3 + c];
        g_W45[t] = s;
    }
    if (t < 3) {
        float s = bout[t];
        for (int j = 0; j < 256; j++) s += b4[j] * Wout[j * 3 + t];
        g_b45[t] = s;
    }
}

// fp32 -> fp16 convert, 8 elements per thread (n % 8 == 0)
__global__ void k_cvt(const float* __restrict__ in, __half* __restrict__ out, int n) {
    int i = (blockIdx.x * blockDim.x + threadIdx.x) * 8;
    if (i >= n) return;
    float4 a = *(const float4*)&in[i];
    float4 b = *(const float4*)&in[i + 4];
    __half2 h0 = __floats2half2_rn(a.x, a.y);
    __half2 h1 = __floats2half2_rn(a.z, a.w);
    __half2 h2 = __floats2half2_rn(b.x, b.y);
    __half2 h3 = __floats2half2_rn(b.z, b.w);
    uint4 pk;
    pk.x = *(unsigned*)&h0; pk.y = *(unsigned*)&h1;
    pk.z = *(unsigned*)&h2; pk.w = *(unsigned*)&h3;
    *(uint4*)&out[i] = pk;
}

// ---------------- HMMA GEMM (wmma): C[N,dout](fp16) = A[N,din](fp16) @ W[din,dout](fp16) ----------------
// block tile 128(M) x 64(N), 256 threads = 8 warps (4m x 2n), warp tile 32x32
__global__ void k_hgemm(const __half* __restrict__ A, const __half* __restrict__ W,
                        const float* __restrict__ bias, __half* __restrict__ C,
                        int din, int dout, int relu) {
    __shared__ __half As[128][24];   // 16 k + 8 pad (48B rows, 16B aligned)
    __shared__ __half Bs[16][72];    // 64 n + 8 pad (144B rows)
    __shared__ float Es[8][256];     // per-warp epilogue patch (16x16)

    int tid = threadIdx.x;
    int lane = tid & 31;
    int wid = tid >> 5;
    int warp_m = wid & 3;            // 0..3
    int warp_n = wid >> 2;           // 0..1
    int row0 = blockIdx.x * 128;
    int col0 = blockIdx.y * 64;

    wmma::fragment<wmma::accumulator, 16, 16, 16, float> acc[2][2];
#pragma unroll
    for (int i = 0; i < 2; i++)
#pragma unroll
        for (int j = 0; j < 2; j++) wmma::fill_fragment(acc[i][j], 0.f);

    for (int k0 = 0; k0 < din; k0 += 16) {
        // A tile: 128x16 halves = 256 x 16B; 1 uint4 per thread
        {
            int r = tid >> 1, c = (tid & 1) * 8;
            uint4 v = make_uint4(0, 0, 0, 0);
            if (row0 + r < N_NODES)
                v = *(const uint4*)&A[(size_t)(row0 + r) * din + k0 + c];
            *(uint4*)&As[r][c] = v;
        }
        // B tile: 16x64 halves = 128 x 16B; threads 0..127
        if (tid < 128) {
            int r = tid >> 3, c = (tid & 7) * 8;
            *(uint4*)&Bs[r][c] = *(const uint4*)&W[(size_t)(k0 + r) * dout + col0 + c];
        }
        __syncthreads();

        wmma::fragment<wmma::matrix_a, 16, 16, 16, __half, wmma::row_major> af[2];
        wmma::fragment<wmma::matrix_b, 16, 16, 16, __half, wmma::row_major> bf[2];
#pragma unroll
        for (int i = 0; i < 2; i++)
            wmma::load_matrix_sync(af[i], &As[warp_m * 32 + i * 16][0], 24);
#pragma unroll
        for (int j = 0; j < 2; j++)
            wmma::load_matrix_sync(bf[j], &Bs[0][warp_n * 32 + j * 16], 72);
#pragma unroll
        for (int i = 0; i < 2; i++)
#pragma unroll
            for (int j = 0; j < 2; j++)
                wmma::mma_sync(acc[i][j], af[i], bf[j], acc[i][j]);
        __syncthreads();
    }

    // epilogue: per-warp smem patch, bias + relu + fp16 pack
#pragma unroll
    for (int i = 0; i < 2; i++) {
#pragma unroll
        for (int j = 0; j < 2; j++) {
            wmma::store_matrix_sync(&Es[wid][0], acc[i][j], 16, wmma::mem_row_major);
            __syncwarp();
            int r = lane >> 1, c = (lane & 1) * 8;
            int gr = row0 + warp_m * 32 + i * 16 + r;
            int gc = col0 + warp_n * 32 + j * 16 + c;
            if (gr < N_NODES) {
                float v[8];
#pragma unroll
                for (int t = 0; t < 8; t++) {
                    float f = Es[wid][r * 16 + c + t];
                    if (bias) f += bias[gc + t];
                    if (relu) f = fmaxf(f, 0.f);
                    v[t] = f;
                }
                __half2 h0 = __floats2half2_rn(v[0], v[1]);
                __half2 h1 = __floats2half2_rn(v[2], v[3]);
                __half2 h2 = __floats2half2_rn(v[4], v[5]);
                __half2 h3 = __floats2half2_rn(v[6], v[7]);
                uint4 pk;
                pk.x = *(unsigned*)&h0; pk.y = *(unsigned*)&h1;
                pk.z = *(unsigned*)&h2; pk.w = *(unsigned*)&h3;
                *(uint4*)&C[(size_t)gr * dout + gc] = pk;
            }
            __syncwarp();
        }
    }
}

// ---------------- aggregation D=64 fp16: 4 edges per warp (8 lanes x 16B each) ----------------
template <bool BIAS, bool RELU>
__global__ void k_agg64(const __half* __restrict__ H, const float* __restrict__ bias,
                        __half* __restrict__ out) {
    int warp = (blockIdx.x * blockDim.x + threadIdx.x) >> 5;
    int lane = threadIdx.x & 31;
    if (warp >= N_NODES) return;
    int grp = lane >> 3, gl = lane & 7;
    const uint4* H4 = (const uint4*)H;   // row = 8 x uint4

    float a[8];
#pragma unroll
    for (int j = 0; j < 8; j++) a[j] = 0.f;

    if (grp == 0) {
        float selfn = g_dis[warp];
        selfn *= selfn;
        uint4 v = H4[(size_t)warp * 8 + gl];
        const __half2* h2 = (const __half2*)&v;
#pragma unroll
        for (int j = 0; j < 4; j++) {
            float2 f = __half22float2(h2[j]);
            a[2 * j] = f.x * selfn;
            a[2 * j + 1] = f.y * selfn;
        }
    }

    int s = g_rowptr[warp];
    int e = s + g_cnt[warp];
    for (int p = s + grp; p < e; p += 4) {
        int src = __ldg(&g_col[p]);
        float w = __ldg(&g_val[p]);
        uint4 v = __ldg(&H4[(size_t)src * 8 + gl]);
        const __half2* h2 = (const __half2*)&v;
#pragma unroll
        for (int j = 0; j < 4; j++) {
            float2 f = __half22float2(h2[j]);
            a[2 * j] += f.x * w;
            a[2 * j + 1] += f.y * w;
        }
    }
    __syncwarp();
#pragma unroll
    for (int j = 0; j < 8; j++) {
        a[j] += __shfl_xor_sync(0xffffffffu, a[j], 8);
        a[j] += __shfl_xor_sync(0xffffffffu, a[j], 16);
    }
    if (grp == 0) {
#pragma unroll
        for (int j = 0; j < 8; j++) {
            if (BIAS) a[j] += bias[gl * 8 + j];
            if (RELU) a[j] = fmaxf(a[j], 0.f);
        }
        __half2 h0 = __floats2half2_rn(a[0], a[1]);
        __half2 h1 = __floats2half2_rn(a[2], a[3]);
        __half2 h2o = __floats2half2_rn(a[4], a[5]);
        __half2 h3 = __floats2half2_rn(a[6], a[7]);
        uint4 pk;
        pk.x = *(unsigned*)&h0; pk.y = *(unsigned*)&h1;
        pk.z = *(unsigned*)&h2o; pk.w = *(unsigned*)&h3;
        ((uint4*)out)[(size_t)warp * 8 + gl] = pk;
    }
}

// ---------------- aggregation D=128 fp16 in/out: 2 edges per warp (16 lanes x 16B) ----------------
__global__ void k_agg128(const __half* __restrict__ H, __half* __restrict__ out) {
    int warp = (blockIdx.x * blockDim.x + threadIdx.x) >> 5;
    int lane = threadIdx.x & 31;
    if (warp >= N_NODES) return;
    int half = lane >> 4, hl = lane & 15;
    const uint4* H4 = (const uint4*)H;   // row = 16 x uint4

    float a[8];
#pragma unroll
    for (int j = 0; j < 8; j++) a[j] = 0.f;

    if (half == 0) {
        float selfn = g_dis[warp];
        selfn *= selfn;
        uint4 v = H4[(size_t)warp * 16 + hl];
        const __half2* h2 = (const __half2*)&v;
#pragma unroll
        for (int j = 0; j < 4; j++) {
            float2 f = __half22float2(h2[j]);
            a[2 * j] = f.x * selfn;
            a[2 * j + 1] = f.y * selfn;
        }
    }

    int s = g_rowptr[warp];
    int e = s + g_cnt[warp];
    for (int p = s + half; p < e; p += 2) {
        int src = __ldg(&g_col[p]);
        float w = __ldg(&g_val[p]);
        uint4 v = __ldg(&H4[(size_t)src * 16 + hl]);
        const __half2* h2 = (const __half2*)&v;
#pragma unroll
        for (int j = 0; j < 4; j++) {
            float2 f = __half22float2(h2[j]);
            a[2 * j] += f.x * w;
            a[2 * j + 1] += f.y * w;
        }
    }
    __syncwarp();
#pragma unroll
    for (int j = 0; j < 8; j++)
        a[j] += __shfl_xor_sync(0xffffffffu, a[j], 16);
    if (half == 0) {
        __half2 h0 = __floats2half2_rn(a[0], a[1]);
        __half2 h1 = __floats2half2_rn(a[2], a[3]);
        __half2 h2o = __floats2half2_rn(a[4], a[5]);
        __half2 h3 = __floats2half2_rn(a[6], a[7]);
        uint4 pk;
        pk.x = *(unsigned*)&h0; pk.y = *(unsigned*)&h1;
        pk.z = *(unsigned*)&h2o; pk.w = *(unsigned*)&h3;
        ((uint4*)out)[(size_t)warp * 16 + hl] = pk;
    }
}

// ---------------- L4 re-association: proj = h3(fp16) @ W45 (N x 3), THEN aggregate at D=3 ----------------
__global__ void k_proj(const __half* __restrict__ H) {
    int warp = (blockIdx.x * blockDim.x + threadIdx.x) >> 5;
    int lane = threadIdx.x & 31;
    if (warp >= N_NODES) return;

    // 256 halves per row = 32 uint4; one per lane
    uint4 v = ((const uint4*)H)[(size_t)warp * 32 + lane];
    const __half2* h2 = (const __half2*)&v;
    float s0 = 0.f, s1 = 0.f, s2 = 0.f;
#pragma unroll
    for (int j = 0; j < 4; j++) {
        float2 f = __half22float2(h2[j]);
        int col = 8 * lane + 2 * j;
        s0 += f.x * g_W45[col * 3 + 0] + f.y * g_W45[(col + 1) * 3 + 0];
        s1 += f.x * g_W45[col * 3 + 1] + f.y * g_W45[(col + 1) * 3 + 1];
        s2 += f.x * g_W45[col * 3 + 2] + f.y * g_W45[(col + 1) * 3 + 2];
    }
#pragma unroll
    for (int off = 16; off; off >>= 1) {
        s0 += __shfl_down_sync(0xffffffffu, s0, off);
        s1 += __shfl_down_sync(0xffffffffu, s1, off);
        s2 += __shfl_down_sync(0xffffffffu, s2, off);
    }
    if (lane == 0) g_proj[warp] = make_float4(s0, s1, s2, 0.f);
}

__global__ void k_agg3(float* __restrict__ out) {
    int v = blockIdx.x * blockDim.x + threadIdx.x;
    if (v >= N_NODES) return;
    float selfn = g_dis[v];
    selfn *= selfn;
    float4 p = g_proj[v];
    float a0 = p.x * selfn, a1 = p.y * selfn, a2 = p.z * selfn;

    int s = g_rowptr[v];
    int e = s + g_cnt[v];
#pragma unroll 2
    for (int q = s; q < e; q++) {
        int src = __ldg(&g_col[q]);
        float w = __ldg(&g_val[q]);
        float4 h = __ldg(&g_proj[src]);
        a0 += h.x * w; a1 += h.y * w; a2 += h.z * w;
    }
    out[(size_t)v * 3 + 0] = a0 + g_b45[0];
    out[(size_t)v * 3 + 1] = a1 + g_b45[1];
    out[(size_t)v * 3 + 2] = a2 + g_b45[2];
}

// ---------------- launch ----------------
extern "C" void kernel_launch(void* const* d_in, const int* in_sizes, int n_in,
                              void* d_out, int out_size) {
    const float* x    = (const float*)d_in[0];
    const void*  ei   = d_in[1];
    const float* ew   = (const float*)d_in[2];
    const float* W1   = (const float*)d_in[3];
    const float* b1   = (const float*)d_in[4];
    const float* W2   = (const float*)d_in[5];
    const float* b2   = (const float*)d_in[6];
    const float* W3   = (const float*)d_in[7];
    const float* b3   = (const float*)d_in[8];
    const float* W4   = (const float*)d_in[9];
    const float* b4   = (const float*)d_in[10];
    const float* Wout = (const float*)d_in[11];
    const float* bout = (const float*)d_in[12];
    float* out = (float*)d_out;

    __half *hx, *hA, *hB, *hW1, *hW2, *hW3;
    cudaGetSymbolAddress((void**)&hx, g_hx);
    cudaGetSymbolAddress((void**)&hA, g_hA);
    cudaGetSymbolAddress((void**)&hB, g_hB);
    cudaGetSymbolAddress((void**)&hW1, g_hW1);
    cudaGetSymbolAddress((void**)&hW2, g_hW2);
    cudaGetSymbolAddress((void**)&hW3, g_hW3);

    static cudaStream_t s2 = nullptr;
    static cudaEvent_t evFork = nullptr, evJoin = nullptr;
    if (!s2) {
        cudaStreamCreateWithFlags(&s2, cudaStreamNonBlocking);
        cudaEventCreateWithFlags(&evFork, cudaEventDisableTiming);
        cudaEventCreateWithFlags(&evJoin, cudaEventDisableTiming);
    }

    const int TB = 256;
    int nodeBlocks = (N_NODES + TB - 1) / TB;
    int edgeBlocks = (N_EDGES + TB - 1) / TB;
    int scanBlocks = (N_NODES + 1023) / 1024;
    int warpNodeBlocks = (N_NODES + 7) / 8;
    int gm = (N_NODES + 127) / 128;

    // fork: conversions + GEMM1 + W45 fold are independent of graph preprocessing
    cudaEventRecord(evFork, 0);
    cudaStreamWaitEvent(s2, evFork, 0);
    k_cvt<<<(N_NODES * 128 / 8 + TB - 1) / TB, TB, 0, s2>>>(x, hx, N_NODES * 128);
    k_cvt<<<(128 * 64 / 8 + TB - 1) / TB, TB, 0, s2>>>(W1, hW1, 128 * 64);
    k_cvt<<<(64 * 128 / 8 + TB - 1) / TB, TB, 0, s2>>>(W2, hW2, 64 * 128);
    k_cvt<<<(128 * 256 / 8 + TB - 1) / TB, TB, 0, s2>>>(W3, hW3, 128 * 256);
    k_hgemm<<<dim3(gm, 1), 256, 0, s2>>>(hx, hW1, nullptr, hA, 128, 64, 0);
    k_w45<<<1, 768, 0, s2>>>(W4, b4, Wout, bout);
    cudaEventRecord(evJoin, s2);

    // main stream: CSR preprocessing
    k_init<<<nodeBlocks, TB>>>();
    k_detect<<<(DETECT_WORDS + TB - 1) / TB, TB>>>((const long long*)ei);
    k_decdeg<<<edgeBlocks, TB>>>(ei, ew);
    k_dis<<<nodeBlocks, TB>>>();
    k_scan1<<<scanBlocks, 1024>>>();
    k_scan2<<<1, 128>>>(scanBlocks);
    k_addoff<<<nodeBlocks, TB>>>();
    k_build<<<edgeBlocks, TB>>>(ei, ew);

    cudaStreamWaitEvent(0, evJoin, 0);

    // L1: h1 = relu(agg(t1) + b1)             t1=hA(64) -> h1=hB(64)
    k_agg64<true, true><<<warpNodeBlocks, 256>>>(hA, b1, hB);

    // L2: h2 = relu(agg(h1) @ W2 + b2)        a2=hA(64); t2=hB(128)
    k_agg64<false, false><<<warpNodeBlocks, 256>>>(hB, nullptr, hA);
    k_hgemm<<<dim3(gm, 2), 256>>>(hA, hW2, b2, hB, 64, 128, 1);

    // L3: h3 = relu(agg(h2) @ W3 + b3)        a3=hA(128); t3=hB(256)
    k_agg128<<<warpNodeBlocks, 256>>>(hB, hA);
    k_hgemm<<<dim3(gm, 4), 256>>>(hA, hW3, b3, hB, 128, 256, 1);

    // L4 + head, re-associated: out = agg(h3 @ W45) + b45
    k_proj<<<warpNodeBlocks, 256>>>(hB);
    k_agg3<<<nodeBlocks, TB>>>(out);

    (void)in_sizes; (void)n_in; (void)out_size;
}

// round 8
// speedup vs baseline: 2.2352x; 1.0196x over previous
#include <cuda_runtime.h>
#include <cuda_fp16.h>
#include <mma.h>

using namespace nvcuda;

#define N_NODES 100000
#define N_EDGES 1600000

typedef unsigned long long ull;

// ---------------- scratch (__device__ globals; no allocation allowed) ----------------
__device__ float g_deg[N_NODES];
__device__ float g_dis[N_NODES];
__device__ int   g_cnt[N_NODES];
__device__ int   g_rowptr[N_NODES];
__device__ int   g_fill[N_NODES];
__device__ int   g_col[N_EDGES];
__device__ float g_val[N_EDGES];
__device__ int   g_bsum[128];
__device__ int   g_is64;
__device__ float g_W45[256 * 3];
__device__ float g_b45[3];
__device__ __half g_hx[(size_t)N_NODES * 128];   // x in fp16
__device__ __half g_hA[(size_t)N_NODES * 256];   // ping
__device__ __half g_hB[(size_t)N_NODES * 256];   // pong
__device__ __half g_hW1[128 * 64];
__device__ __half g_hW2[64 * 128];
__device__ __half g_hW3[128 * 256];
__device__ float4 g_proj[N_NODES];

// ---------------- setup kernels ----------------
__global__ void k_init() {
    int i = blockIdx.x * blockDim.x + threadIdx.x;
    if (i < N_NODES) { g_deg[i] = 1.0f; g_cnt[i] = 0; }
    if (i == 0) g_is64 = 1;
}

#define DETECT_WORDS (1 << 18)
__global__ void k_detect(const long long* __restrict__ ei) {
    int i = blockIdx.x * blockDim.x + threadIdx.x;
    if (i < DETECT_WORDS) {
        unsigned long long v = (unsigned long long)ei[i];
        if (v >= (unsigned long long)N_NODES) g_is64 = 0;
    }
}

__device__ __forceinline__ void decode_edge(const void* eiv, int e, int& s, int& d) {
    if (g_is64) {
        const long long* ei = (const long long*)eiv;
        s = (int)ei[e];
        d = (int)ei[N_EDGES + e];
    } else {
        const int* ei = (const int*)eiv;
        s = ei[e];
        d = ei[N_EDGES + e];
    }
}

__global__ void k_decdeg(const void* __restrict__ eiv, const float* __restrict__ ew) {
    int e = blockIdx.x * blockDim.x + threadIdx.x;
    if (e >= N_EDGES) return;
    int s, d;
    decode_edge(eiv, e, s, d);
    atomicAdd(&g_deg[d], ew[e]);
    atomicAdd(&g_cnt[d], 1);
}

__global__ void k_dis() {
    int i = blockIdx.x * blockDim.x + threadIdx.x;
    if (i < N_NODES) g_dis[i] = rsqrtf(g_deg[i]);
}

__global__ void k_scan1() {
    __shared__ int s[1024];
    int tid = threadIdx.x;
    int i = blockIdx.x * 1024 + tid;
    int v = (i < N_NODES) ? g_cnt[i] : 0;
    s[tid] = v;
    __syncthreads();
    for (int off = 1; off < 1024; off <<= 1) {
        int t = (tid >= off) ? s[tid - off] : 0;
        __syncthreads();
        s[tid] += t;
        __syncthreads();
    }
    if (i < N_NODES) g_rowptr[i] = s[tid] - v;
    if (tid == 1023) g_bsum[blockIdx.x] = s[tid];
}

__global__ void k_scan2(int nb) {
    __shared__ int s[128];
    int tid = threadIdx.x;
    int v = (tid < nb) ? g_bsum[tid] : 0;
    s[tid] = v;
    __syncthreads();
    for (int off = 1; off < 128; off <<= 1) {
        int t = (tid >= off) ? s[tid - off] : 0;
        __syncthreads();
        s[tid] += t;
        __syncthreads();
    }
    if (tid < nb) g_bsum[tid] = s[tid] - v;
}

__global__ void k_addoff() {
    int i = blockIdx.x * blockDim.x + threadIdx.x;
    if (i < N_NODES) {
        int r = g_rowptr[i] + g_bsum[i >> 10];
        g_rowptr[i] = r;
        g_fill[i] = r;
    }
}

__global__ void k_build(const void* __restrict__ eiv, const float* __restrict__ ew) {
    int e = blockIdx.x * blockDim.x + threadIdx.x;
    if (e >= N_EDGES) return;
    int s, d;
    decode_edge(eiv, e, s, d);
    float nm = g_dis[s] * ew[e] * g_dis[d];
    int p = atomicAdd(&g_fill[d], 1);
    g_col[p] = s;
    g_val[p] = nm;
}

__global__ void k_w45(const float* __restrict__ W4, const float* __restrict__ b4,
                      const float* __restrict__ Wout, const float* __restrict__ bout) {
    int t = blockIdx.x * blockDim.x + threadIdx.x;
    if (t < 256 * 3) {
        int k = t / 3, c = t % 3;
        float s = 0.f;
        for (int j = 0; j < 256; j++) s += W4[k * 256 + j] * Wout[j * 3 + c];
        g_W45[t] = s;
    }
    if (t < 3) {
        float s = bout[t];
        for (int j = 0; j < 256; j++) s += b4[j] * Wout[j * 3 + t];
        g_b45[t] = s;
    }
}

// fp32 -> fp16 convert, 8 elements per thread (n % 8 == 0)
__global__ void k_cvt(const float* __restrict__ in, __half* __restrict__ out, int n) {
    int i = (blockIdx.x * blockDim.x + threadIdx.x) * 8;
    if (i >= n) return;
    float4 a = *(const float4*)&in[i];
    float4 b = *(const float4*)&in[i + 4];
    __half2 h0 = __floats2half2_rn(a.x, a.y);
    __half2 h1 = __floats2half2_rn(a.z, a.w);
    __half2 h2 = __floats2half2_rn(b.x, b.y);
    __half2 h3 = __floats2half2_rn(b.z, b.w);
    uint4 pk;
    pk.x = *(unsigned*)&h0; pk.y = *(unsigned*)&h1;
    pk.z = *(unsigned*)&h2; pk.w = *(unsigned*)&h3;
    *(uint4*)&out[i] = pk;
}

// convert all three weight matrices in one launch (49152 elems, 8 per thread)
__global__ void k_cvtw(const float* __restrict__ W1, const float* __restrict__ W2,
                       const float* __restrict__ W3, __half* __restrict__ h1,
                       __half* __restrict__ h2, __half* __restrict__ h3) {
    int i = (blockIdx.x * blockDim.x + threadIdx.x) * 8;
    const float* in;
    __half* out;
    if (i < 8192) { in = W1; out = h1; }
    else if (i < 16384) { in = W2 + (i - 8192) - (i - 8192); in = W2; out = h2; i -= 8192; }
    else { in = W3; out = h3; i -= 16384; if (i >= 32768) return; }
    float4 a = *(const float4*)&in[i];
    float4 b = *(const float4*)&in[i + 4];
    __half2 q0 = __floats2half2_rn(a.x, a.y);
    __half2 q1 = __floats2half2_rn(a.z, a.w);
    __half2 q2 = __floats2half2_rn(b.x, b.y);
    __half2 q3 = __floats2half2_rn(b.z, b.w);
    uint4 pk;
    pk.x = *(unsigned*)&q0; pk.y = *(unsigned*)&q1;
    pk.z = *(unsigned*)&q2; pk.w = *(unsigned*)&q3;
    *(uint4*)&out[i] = pk;
}

// ---------------- HMMA GEMM (wmma): double-buffered, BK=32 ----------------
// block tile 128(M) x 64(N), 256 threads = 8 warps (4m x 2n), warp tile 32x32
__global__ void k_hgemm(const __half* __restrict__ A, const __half* __restrict__ W,
                        const float* __restrict__ bias, __half* __restrict__ C,
                        int din, int dout, int relu) {
    __shared__ __half As[2][128][40];   // 32 k + 8 pad
    __shared__ __half Bs[2][32][72];    // 64 n + 8 pad
    __shared__ float Es[8][256];        // per-warp epilogue patch (16x16)

    int tid = threadIdx.x;
    int lane = tid & 31;
    int wid = tid >> 5;
    int warp_m = wid & 3;
    int warp_n = wid >> 2;
    int row0 = blockIdx.x * 128;
    int col0 = blockIdx.y * 64;

    // A: 128 rows x 32 halves = 512 uint4; 2 per thread
    int ar0 = tid >> 1, ac0 = (tid & 1) * 8;            // +16 halves for second
    int br = tid >> 3, bc = (tid & 7) * 8;              // B: 32 x 64 halves = 256 uint4

    wmma::fragment<wmma::accumulator, 16, 16, 16, float> acc[2][2];
#pragma unroll
    for (int i = 0; i < 2; i++)
#pragma unroll
        for (int j = 0; j < 2; j++) wmma::fill_fragment(acc[i][j], 0.f);

    int nk = din >> 5;

    // prologue: tile 0 -> buffer 0
    {
        uint4 v0 = make_uint4(0, 0, 0, 0), v1 = v0;
        if (row0 + ar0 < N_NODES) {
            v0 = *(const uint4*)&A[(size_t)(row0 + ar0) * din + ac0];
            v1 = *(const uint4*)&A[(size_t)(row0 + ar0) * din + ac0 + 16];
        }
        *(uint4*)&As[0][ar0][ac0] = v0;
        *(uint4*)&As[0][ar0][ac0 + 16] = v1;
        *(uint4*)&Bs[0][br][bc] = *(const uint4*)&W[(size_t)br * dout + col0 + bc];
    }
    __syncthreads();

    for (int kt = 0; kt < nk; kt++) {
        int cur = kt & 1;
        bool more = (kt + 1 < nk);
        uint4 p0, p1, pb;
        if (more) {
            int k0 = (kt + 1) << 5;
            p0 = make_uint4(0, 0, 0, 0); p1 = p0;
            if (row0 + ar0 < N_NODES) {
                p0 = *(const uint4*)&A[(size_t)(row0 + ar0) * din + k0 + ac0];
                p1 = *(const uint4*)&A[(size_t)(row0 + ar0) * din + k0 + ac0 + 16];
            }
            pb = *(const uint4*)&W[(size_t)(k0 + br) * dout + col0 + bc];
        }
        // compute 2 x K16 on current buffer
#pragma unroll
        for (int ks = 0; ks < 2; ks++) {
            wmma::fragment<wmma::matrix_a, 16, 16, 16, __half, wmma::row_major> af[2];
            wmma::fragment<wmma::matrix_b, 16, 16, 16, __half, wmma::row_major> bf[2];
#pragma unroll
            for (int i = 0; i < 2; i++)
                wmma::load_matrix_sync(af[i], &As[cur][warp_m * 32 + i * 16][ks * 16], 40);
#pragma unroll
            for (int j = 0; j < 2; j++)
                wmma::load_matrix_sync(bf[j], &Bs[cur][ks * 16][warp_n * 32 + j * 16], 72);
#pragma unroll
            for (int i = 0; i < 2; i++)
#pragma unroll
                for (int j = 0; j < 2; j++)
                    wmma::mma_sync(acc[i][j], af[i], bf[j], acc[i][j]);
        }
        if (more) {
            int nxt = cur ^ 1;
            *(uint4*)&As[nxt][ar0][ac0] = p0;
            *(uint4*)&As[nxt][ar0][ac0 + 16] = p1;
            *(uint4*)&Bs[nxt][br][bc] = pb;
            __syncthreads();
        }
    }

    // epilogue: per-warp smem patch, bias + relu + fp16 pack
#pragma unroll
    for (int i = 0; i < 2; i++) {
#pragma unroll
        for (int j = 0; j < 2; j++) {
            wmma::store_matrix_sync(&Es[wid][0], acc[i][j], 16, wmma::mem_row_major);
            __syncwarp();
            int r = lane >> 1, c = (lane & 1) * 8;
            int gr = row0 + warp_m * 32 + i * 16 + r;
            int gc = col0 + warp_n * 32 + j * 16 + c;
            if (gr < N_NODES) {
                float v[8];
#pragma unroll
                for (int t = 0; t < 8; t++) {
                    float f = Es[wid][r * 16 + c + t];
                    if (bias) f += bias[gc + t];
                    if (relu) f = fmaxf(f, 0.f);
                    v[t] = f;
                }
                __half2 h0 = __floats2half2_rn(v[0], v[1]);
                __half2 h1 = __floats2half2_rn(v[2], v[3]);
                __half2 h2 = __floats2half2_rn(v[4], v[5]);
                __half2 h3 = __floats2half2_rn(v[6], v[7]);
                uint4 pk;
                pk.x = *(unsigned*)&h0; pk.y = *(unsigned*)&h1;
                pk.z = *(unsigned*)&h2; pk.w = *(unsigned*)&h3;
                *(uint4*)&C[(size_t)gr * dout + gc] = pk;
            }
            __syncwarp();
        }
    }
}

// ---------------- aggregation D=64 fp16: 4 edges per warp (8 lanes x 16B each) ----------------
template <bool BIAS, bool RELU>
__global__ void k_agg64(const __half* __restrict__ H, const float* __restrict__ bias,
                        __half* __restrict__ out) {
    int warp = (blockIdx.x * blockDim.x + threadIdx.x) >> 5;
    int lane = threadIdx.x & 31;
    if (warp >= N_NODES) return;
    int grp = lane >> 3, gl = lane & 7;
    const uint4* H4 = (const uint4*)H;   // row = 8 x uint4

    float a[8];
#pragma unroll
    for (int j = 0; j < 8; j++) a[j] = 0.f;

    if (grp == 0) {
        float selfn = g_dis[warp];
        selfn *= selfn;
        uint4 v = H4[(size_t)warp * 8 + gl];
        const __half2* h2 = (const __half2*)&v;
#pragma unroll
        for (int j = 0; j < 4; j++) {
            float2 f = __half22float2(h2[j]);
            a[2 * j] = f.x * selfn;
            a[2 * j + 1] = f.y * selfn;
        }
    }

    int s = g_rowptr[warp];
    int e = s + g_cnt[warp];
    for (int p = s + grp; p < e; p += 4) {
        int src = __ldg(&g_col[p]);
        float w = __ldg(&g_val[p]);
        uint4 v = __ldg(&H4[(size_t)src * 8 + gl]);
        const __half2* h2 = (const __half2*)&v;
#pragma unroll
        for (int j = 0; j < 4; j++) {
            float2 f = __half22float2(h2[j]);
            a[2 * j] += f.x * w;
            a[2 * j + 1] += f.y * w;
        }
    }
    __syncwarp();
#pragma unroll
    for (int j = 0; j < 8; j++) {
        a[j] += __shfl_xor_sync(0xffffffffu, a[j], 8);
        a[j] += __shfl_xor_sync(0xffffffffu, a[j], 16);
    }
    if (grp == 0) {
#pragma unroll
        for (int j = 0; j < 8; j++) {
            if (BIAS) a[j] += bias[gl * 8 + j];
            if (RELU) a[j] = fmaxf(a[j], 0.f);
        }
        __half2 h0 = __floats2half2_rn(a[0], a[1]);
        __half2 h1 = __floats2half2_rn(a[2], a[3]);
        __half2 h2o = __floats2half2_rn(a[4], a[5]);
        __half2 h3 = __floats2half2_rn(a[6], a[7]);
        uint4 pk;
        pk.x = *(unsigned*)&h0; pk.y = *(unsigned*)&h1;
        pk.z = *(unsigned*)&h2o; pk.w = *(unsigned*)&h3;
        ((uint4*)out)[(size_t)warp * 8 + gl] = pk;
    }
}

// ---------------- aggregation D=128 fp16 in/out: 2 edges per warp (16 lanes x 16B) ----------------
__global__ void k_agg128(const __half* __restrict__ H, __half* __restrict__ out) {
    int warp = (blockIdx.x * blockDim.x + threadIdx.x) >> 5;
    int lane = threadIdx.x & 31;
    if (warp >= N_NODES) return;
    int half = lane >> 4, hl = lane & 15;
    const uint4* H4 = (const uint4*)H;   // row = 16 x uint4

    float a[8];
#pragma unroll
    for (int j = 0; j < 8; j++) a[j] = 0.f;

    if (half == 0) {
        float selfn = g_dis[warp];
        selfn *= selfn;
        uint4 v = H4[(size_t)warp * 16 + hl];
        const __half2* h2 = (const __half2*)&v;
#pragma unroll
        for (int j = 0; j < 4; j++) {
            float2 f = __half22float2(h2[j]);
            a[2 * j] = f.x * selfn;
            a[2 * j + 1] = f.y * selfn;
        }
    }

    int s = g_rowptr[warp];
    int e = s + g_cnt[warp];
    for (int p = s + half; p < e; p += 2) {
        int src = __ldg(&g_col[p]);
        float w = __ldg(&g_val[p]);
        uint4 v = __ldg(&H4[(size_t)src * 16 + hl]);
        const __half2* h2 = (const __half2*)&v;
#pragma unroll
        for (int j = 0; j < 4; j++) {
            float2 f = __half22float2(h2[j]);
            a[2 * j] += f.x * w;
            a[2 * j + 1] += f.y * w;
        }
    }
    __syncwarp();
#pragma unroll
    for (int j = 0; j < 8; j++)
        a[j] += __shfl_xor_sync(0xffffffffu, a[j], 16);
    if (half == 0) {
        __half2 h0 = __floats2half2_rn(a[0], a[1]);
        __half2 h1 = __floats2half2_rn(a[2], a[3]);
        __half2 h2o = __floats2half2_rn(a[4], a[5]);
        __half2 h3 = __floats2half2_rn(a[6], a[7]);
        uint4 pk;
        pk.x = *(unsigned*)&h0; pk.y = *(unsigned*)&h1;
        pk.z = *(unsigned*)&h2o; pk.w = *(unsigned*)&h3;
        ((uint4*)out)[(size_t)warp * 16 + hl] = pk;
    }
}

// ---------------- L4 re-association: proj = h3(fp16) @ W45 (N x 3), THEN aggregate at D=3 ----------------
__global__ void k_proj(const __half* __restrict__ H) {
    int warp = (blockIdx.x * blockDim.x + threadIdx.x) >> 5;
    int lane = threadIdx.x & 31;
    if (warp >= N_NODES) return;

    uint4 v = ((const uint4*)H)[(size_t)warp * 32 + lane];
    const __half2* h2 = (const __half2*)&v;
    float s0 = 0.f, s1 = 0.f, s2 = 0.f;
#pragma unroll
    for (int j = 0; j < 4; j++) {
        float2 f = __half22float2(h2[j]);
        int col = 8 * lane + 2 * j;
        s0 += f.x * g_W45[col * 3 + 0] + f.y * g_W45[(col + 1) * 3 + 0];
        s1 += f.x * g_W45[col * 3 + 1] + f.y * g_W45[(col + 1) * 3 + 1];
        s2 += f.x * g_W45[col * 3 + 2] + f.y * g_W45[(col + 1) * 3 + 2];
    }
#pragma unroll
    for (int off = 16; off; off >>= 1) {
        s0 += __shfl_down_sync(0xffffffffu, s0, off);
        s1 += __shfl_down_sync(0xffffffffu, s1, off);
        s2 += __shfl_down_sync(0xffffffffu, s2, off);
    }
    if (lane == 0) g_proj[warp] = make_float4(s0, s1, s2, 0.f);
}

__global__ void k_agg3(float* __restrict__ out) {
    int v = blockIdx.x * blockDim.x + threadIdx.x;
    if (v >= N_NODES) return;
    float selfn = g_dis[v];
    selfn *= selfn;
    float4 p = g_proj[v];
    float a0 = p.x * selfn, a1 = p.y * selfn, a2 = p.z * selfn;

    int s = g_rowptr[v];
    int e = s + g_cnt[v];
#pragma unroll 2
    for (int q = s; q < e; q++) {
        int src = __ldg(&g_col[q]);
        float w = __ldg(&g_val[q]);
        float4 h = __ldg(&g_proj[src]);
        a0 += h.x * w; a1 += h.y * w; a2 += h.z * w;
    }
    out[(size_t)v * 3 + 0] = a0 + g_b45[0];
    out[(size_t)v * 3 + 1] = a1 + g_b45[1];
    out[(size_t)v * 3 + 2] = a2 + g_b45[2];
}

// ---------------- launch ----------------
extern "C" void kernel_launch(void* const* d_in, const int* in_sizes, int n_in,
                              void* d_out, int out_size) {
    const float* x    = (const float*)d_in[0];
    const void*  ei   = d_in[1];
    const float* ew   = (const float*)d_in[2];
    const float* W1   = (const float*)d_in[3];
    const float* b1   = (const float*)d_in[4];
    const float* W2   = (const float*)d_in[5];
    const float* b2   = (const float*)d_in[6];
    const float* W3   = (const float*)d_in[7];
    const float* b3   = (const float*)d_in[8];
    const float* W4   = (const float*)d_in[9];
    const float* b4   = (const float*)d_in[10];
    const float* Wout = (const float*)d_in[11];
    const float* bout = (const float*)d_in[12];
    float* out = (float*)d_out;

    __half *hx, *hA, *hB, *hW1, *hW2, *hW3;
    cudaGetSymbolAddress((void**)&hx, g_hx);
    cudaGetSymbolAddress((void**)&hA, g_hA);
    cudaGetSymbolAddress((void**)&hB, g_hB);
    cudaGetSymbolAddress((void**)&hW1, g_hW1);
    cudaGetSymbolAddress((void**)&hW2, g_hW2);
    cudaGetSymbolAddress((void**)&hW3, g_hW3);

    static cudaStream_t s2 = nullptr;
    static cudaEvent_t evFork = nullptr, evJoin = nullptr;
    if (!s2) {
        cudaStreamCreateWithFlags(&s2, cudaStreamNonBlocking);
        cudaEventCreateWithFlags(&evFork, cudaEventDisableTiming);
        cudaEventCreateWithFlags(&evJoin, cudaEventDisableTiming);
    }

    const int TB = 256;
    int nodeBlocks = (N_NODES + TB - 1) / TB;
    int edgeBlocks = (N_EDGES + TB - 1) / TB;
    int scanBlocks = (N_NODES + 1023) / 1024;
    int warpNodeBlocks = (N_NODES + 7) / 8;
    int gm = (N_NODES + 127) / 128;

    // fork: conversions + GEMM1 + W45 fold are independent of graph preprocessing
    cudaEventRecord(evFork, 0);
    cudaStreamWaitEvent(s2, evFork, 0);
    k_cvt<<<(N_NODES * 128 / 8 + TB - 1) / TB, TB, 0, s2>>>(x, hx, N_NODES * 128);
    k_cvtw<<<(49152 / 8 + TB - 1) / TB, TB, 0, s2>>>(W1, W2, W3, hW1, hW2, hW3);
    k_hgemm<<<dim3(gm, 1), 256, 0, s2>>>(hx, hW1, nullptr, hA, 128, 64, 0);
    k_w45<<<1, 768, 0, s2>>>(W4, b4, Wout, bout);
    cudaEventRecord(evJoin, s2);

    // main stream: CSR preprocessing
    k_init<<<nodeBlocks, TB>>>();
    k_detect<<<(DETECT_WORDS + TB - 1) / TB, TB>>>((const long long*)ei);
    k_decdeg<<<edgeBlocks, TB>>>(ei, ew);
    k_dis<<<nodeBlocks, TB>>>();
    k_scan1<<<scanBlocks, 1024>>>();
    k_scan2<<<1, 128>>>(scanBlocks);
    k_addoff<<<nodeBlocks, TB>>>();
    k_build<<<edgeBlocks, TB>>>(ei, ew);

    cudaStreamWaitEvent(0, evJoin, 0);

    // L1: h1 = relu(agg(t1) + b1)             t1=hA(64) -> h1=hB(64)
    k_agg64<true, true><<<warpNodeBlocks, 256>>>(hA, b1, hB);

    // L2: h2 = relu(agg(h1) @ W2 + b2)        a2=hA(64); t2=hB(128)
    k_agg64<false, false><<<warpNodeBlocks, 256>>>(hB, nullptr, hA);
    k_hgemm<<<dim3(gm, 2), 256>>>(hA, hW2, b2, hB, 64, 128, 1);

    // L3: h3 = relu(agg(h2) @ W3 + b3)        a3=hA(128); t3=hB(256)
    k_agg128<<<warpNodeBlocks, 256>>>(hB, hA);
    k_hgemm<<<dim3(gm, 4), 256>>>(hA, hW3, b3, hB, 128, 256, 1);

    // L4 + head, re-associated: out = agg(h3 @ W45) + b45
    k_proj<<<warpNodeBlocks, 256>>>(hB);
    k_agg3<<<nodeBlocks, TB>>>(out);

    (void)in_sizes; (void)n_in; (void)out_size;
}

// round 9
// speedup vs baseline: 2.3806x; 1.0651x over previous
#include <cuda_runtime.h>
#include <cuda_fp16.h>
#include <mma.h>

using namespace nvcuda;

#define N_NODES 100000
#define N_EDGES 1600000

typedef unsigned long long ull;

// ---------------- scratch (__device__ globals; no allocation allowed) ----------------
__device__ float g_deg[N_NODES];
__device__ float g_dis[N_NODES];
__device__ int   g_cnt[N_NODES];
__device__ int   g_rowptr[N_NODES];
__device__ int   g_fill[N_NODES];
__device__ int   g_col[N_EDGES];
__device__ float g_val[N_EDGES];
__device__ int   g_bsum[128];
__device__ int   g_is64;
__device__ float g_W45[256 * 3];
__device__ float g_b45[3];
__device__ __half g_hx[(size_t)N_NODES * 128];   // x in fp16
__device__ __half g_hA[(size_t)N_NODES * 256];   // ping
__device__ __half g_hB[(size_t)N_NODES * 256];   // pong
__device__ __half g_hW1[128 * 64];
__device__ __half g_hW2[64 * 128];
__device__ __half g_hW3[128 * 256];
__device__ float4 g_proj[N_NODES];

// ---------------- setup kernels ----------------
__global__ void k_init() {
    int i = blockIdx.x * blockDim.x + threadIdx.x;
    if (i < N_NODES) { g_deg[i] = 1.0f; g_cnt[i] = 0; }
    if (i == 0) g_is64 = 1;
}

#define DETECT_WORDS (1 << 18)
__global__ void k_detect(const long long* __restrict__ ei) {
    int i = blockIdx.x * blockDim.x + threadIdx.x;
    if (i < DETECT_WORDS) {
        unsigned long long v = (unsigned long long)ei[i];
        if (v >= (unsigned long long)N_NODES) g_is64 = 0;
    }
}

__device__ __forceinline__ void decode_edge(const void* eiv, int e, int& s, int& d) {
    if (g_is64) {
        const long long* ei = (const long long*)eiv;
        s = (int)ei[e];
        d = (int)ei[N_EDGES + e];
    } else {
        const int* ei = (const int*)eiv;
        s = ei[e];
        d = ei[N_EDGES + e];
    }
}

__global__ void k_decdeg(const void* __restrict__ eiv, const float* __restrict__ ew) {
    int e = blockIdx.x * blockDim.x + threadIdx.x;
    if (e >= N_EDGES) return;
    int s, d;
    decode_edge(eiv, e, s, d);
    atomicAdd(&g_deg[d], ew[e]);
    atomicAdd(&g_cnt[d], 1);
}

__global__ void k_dis() {
    int i = blockIdx.x * blockDim.x + threadIdx.x;
    if (i < N_NODES) g_dis[i] = rsqrtf(g_deg[i]);
}

__global__ void k_scan1() {
    __shared__ int s[1024];
    int tid = threadIdx.x;
    int i = blockIdx.x * 1024 + tid;
    int v = (i < N_NODES) ? g_cnt[i] : 0;
    s[tid] = v;
    __syncthreads();
    for (int off = 1; off < 1024; off <<= 1) {
        int t = (tid >= off) ? s[tid - off] : 0;
        __syncthreads();
        s[tid] += t;
        __syncthreads();
    }
    if (i < N_NODES) g_rowptr[i] = s[tid] - v;
    if (tid == 1023) g_bsum[blockIdx.x] = s[tid];
}

__global__ void k_scan2(int nb) {
    __shared__ int s[128];
    int tid = threadIdx.x;
    int v = (tid < nb) ? g_bsum[tid] : 0;
    s[tid] = v;
    __syncthreads();
    for (int off = 1; off < 128; off <<= 1) {
        int t = (tid >= off) ? s[tid - off] : 0;
        __syncthreads();
        s[tid] += t;
        __syncthreads();
    }
    if (tid < nb) g_bsum[tid] = s[tid] - v;
}

__global__ void k_addoff() {
    int i = blockIdx.x * blockDim.x + threadIdx.x;
    if (i < N_NODES) {
        int r = g_rowptr[i] + g_bsum[i >> 10];
        g_rowptr[i] = r;
        g_fill[i] = r;
    }
}

__global__ void k_build(const void* __restrict__ eiv, const float* __restrict__ ew) {
    int e = blockIdx.x * blockDim.x + threadIdx.x;
    if (e >= N_EDGES) return;
    int s, d;
    decode_edge(eiv, e, s, d);
    float nm = g_dis[s] * ew[e] * g_dis[d];
    int p = atomicAdd(&g_fill[d], 1);
    g_col[p] = s;
    g_val[p] = nm;
}

// parallel fold: W45[k][c] = sum_j W4[k][j] * Wout[j][c]; one warp per output
__global__ void k_w45(const float* __restrict__ W4, const float* __restrict__ b4,
                      const float* __restrict__ Wout, const float* __restrict__ bout) {
    int gw = (blockIdx.x * blockDim.x + threadIdx.x) >> 5;   // global warp id
    int lane = threadIdx.x & 31;
    if (gw < 768) {
        int k = gw / 3, c = gw % 3;
        float s = 0.f;
#pragma unroll
        for (int j = lane; j < 256; j += 32)
            s += W4[k * 256 + j] * Wout[j * 3 + c];
#pragma unroll
        for (int off = 16; off; off >>= 1)
            s += __shfl_down_sync(0xffffffffu, s, off);
        if (lane == 0) g_W45[gw] = s;
    } else if (gw < 771) {
        int c = gw - 768;
        float s = 0.f;
#pragma unroll
        for (int j = lane; j < 256; j += 32)
            s += b4[j] * Wout[j * 3 + c];
#pragma unroll
        for (int off = 16; off; off >>= 1)
            s += __shfl_down_sync(0xffffffffu, s, off);
        if (lane == 0) g_b45[c] = s + bout[c];
    }
}

// fp32 -> fp16 convert, 8 elements per thread (n % 8 == 0)
__global__ void k_cvt(const float* __restrict__ in, __half* __restrict__ out, int n) {
    int i = (blockIdx.x * blockDim.x + threadIdx.x) * 8;
    if (i >= n) return;
    float4 a = *(const float4*)&in[i];
    float4 b = *(const float4*)&in[i + 4];
    __half2 h0 = __floats2half2_rn(a.x, a.y);
    __half2 h1 = __floats2half2_rn(a.z, a.w);
    __half2 h2 = __floats2half2_rn(b.x, b.y);
    __half2 h3 = __floats2half2_rn(b.z, b.w);
    uint4 pk;
    pk.x = *(unsigned*)&h0; pk.y = *(unsigned*)&h1;
    pk.z = *(unsigned*)&h2; pk.w = *(unsigned*)&h3;
    *(uint4*)&out[i] = pk;
}

// convert all three weight matrices in one launch (49152 elems, 8 per thread)
__global__ void k_cvtw(const float* __restrict__ W1, const float* __restrict__ W2,
                       const float* __restrict__ W3, __half* __restrict__ h1,
                       __half* __restrict__ h2, __half* __restrict__ h3) {
    int i = (blockIdx.x * blockDim.x + threadIdx.x) * 8;
    const float* in;
    __half* out;
    if (i < 8192) { in = W1; out = h1; }
    else if (i < 16384) { in = W2; out = h2; i -= 8192; }
    else { in = W3; out = h3; i -= 16384; if (i >= 32768) return; }
    float4 a = *(const float4*)&in[i];
    float4 b = *(const float4*)&in[i + 4];
    __half2 q0 = __floats2half2_rn(a.x, a.y);
    __half2 q1 = __floats2half2_rn(a.z, a.w);
    __half2 q2 = __floats2half2_rn(b.x, b.y);
    __half2 q3 = __floats2half2_rn(b.z, b.w);
    uint4 pk;
    pk.x = *(unsigned*)&q0; pk.y = *(unsigned*)&q1;
    pk.z = *(unsigned*)&q2; pk.w = *(unsigned*)&q3;
    *(uint4*)&out[i] = pk;
}

// ---------------- HMMA GEMM (wmma): double-buffered, BK=32 ----------------
// block tile 128(M) x 64(N), 256 threads = 8 warps (4m x 2n), warp tile 32x32
__global__ void k_hgemm(const __half* __restrict__ A, const __half* __restrict__ W,
                        const float* __restrict__ bias, __half* __restrict__ C,
                        int din, int dout, int relu) {
    __shared__ __half As[2][128][40];   // 32 k + 8 pad
    __shared__ __half Bs[2][32][72];    // 64 n + 8 pad
    __shared__ float Es[8][256];        // per-warp epilogue patch (16x16)

    int tid = threadIdx.x;
    int lane = tid & 31;
    int wid = tid >> 5;
    int warp_m = wid & 3;
    int warp_n = wid >> 2;
    int row0 = blockIdx.x * 128;
    int col0 = blockIdx.y * 64;

    int ar0 = tid >> 1, ac0 = (tid & 1) * 8;
    int br = tid >> 3, bc = (tid & 7) * 8;

    wmma::fragment<wmma::accumulator, 16, 16, 16, float> acc[2][2];
#pragma unroll
    for (int i = 0; i < 2; i++)
#pragma unroll
        for (int j = 0; j < 2; j++) wmma::fill_fragment(acc[i][j], 0.f);

    int nk = din >> 5;

    {
        uint4 v0 = make_uint4(0, 0, 0, 0), v1 = v0;
        if (row0 + ar0 < N_NODES) {
            v0 = *(const uint4*)&A[(size_t)(row0 + ar0) * din + ac0];
            v1 = *(const uint4*)&A[(size_t)(row0 + ar0) * din + ac0 + 16];
        }
        *(uint4*)&As[0][ar0][ac0] = v0;
        *(uint4*)&As[0][ar0][ac0 + 16] = v1;
        *(uint4*)&Bs[0][br][bc] = *(const uint4*)&W[(size_t)br * dout + col0 + bc];
    }
    __syncthreads();

    for (int kt = 0; kt < nk; kt++) {
        int cur = kt & 1;
        bool more = (kt + 1 < nk);
        uint4 p0, p1, pb;
        if (more) {
            int k0 = (kt + 1) << 5;
            p0 = make_uint4(0, 0, 0, 0); p1 = p0;
            if (row0 + ar0 < N_NODES) {
                p0 = *(const uint4*)&A[(size_t)(row0 + ar0) * din + k0 + ac0];
                p1 = *(const uint4*)&A[(size_t)(row0 + ar0) * din + k0 + ac0 + 16];
            }
            pb = *(const uint4*)&W[(size_t)(k0 + br) * dout + col0 + bc];
        }
#pragma unroll
        for (int ks = 0; ks < 2; ks++) {
            wmma::fragment<wmma::matrix_a, 16, 16, 16, __half, wmma::row_major> af[2];
            wmma::fragment<wmma::matrix_b, 16, 16, 16, __half, wmma::row_major> bf[2];
#pragma unroll
            for (int i = 0; i < 2; i++)
                wmma::load_matrix_sync(af[i], &As[cur][warp_m * 32 + i * 16][ks * 16], 40);
#pragma unroll
            for (int j = 0; j < 2; j++)
                wmma::load_matrix_sync(bf[j], &Bs[cur][ks * 16][warp_n * 32 + j * 16], 72);
#pragma unroll
            for (int i = 0; i < 2; i++)
#pragma unroll
                for (int j = 0; j < 2; j++)
                    wmma::mma_sync(acc[i][j], af[i], bf[j], acc[i][j]);
        }
        if (more) {
            int nxt = cur ^ 1;
            *(uint4*)&As[nxt][ar0][ac0] = p0;
            *(uint4*)&As[nxt][ar0][ac0 + 16] = p1;
            *(uint4*)&Bs[nxt][br][bc] = pb;
            __syncthreads();
        }
    }

#pragma unroll
    for (int i = 0; i < 2; i++) {
#pragma unroll
        for (int j = 0; j < 2; j++) {
            wmma::store_matrix_sync(&Es[wid][0], acc[i][j], 16, wmma::mem_row_major);
            __syncwarp();
            int r = lane >> 1, c = (lane & 1) * 8;
            int gr = row0 + warp_m * 32 + i * 16 + r;
            int gc = col0 + warp_n * 32 + j * 16 + c;
            if (gr < N_NODES) {
                float v[8];
#pragma unroll
                for (int t = 0; t < 8; t++) {
                    float f = Es[wid][r * 16 + c + t];
                    if (bias) f += bias[gc + t];
                    if (relu) f = fmaxf(f, 0.f);
                    v[t] = f;
                }
                __half2 h0 = __floats2half2_rn(v[0], v[1]);
                __half2 h1 = __floats2half2_rn(v[2], v[3]);
                __half2 h2 = __floats2half2_rn(v[4], v[5]);
                __half2 h3 = __floats2half2_rn(v[6], v[7]);
                uint4 pk;
                pk.x = *(unsigned*)&h0; pk.y = *(unsigned*)&h1;
                pk.z = *(unsigned*)&h2; pk.w = *(unsigned*)&h3;
                *(uint4*)&C[(size_t)gr * dout + gc] = pk;
            }
            __syncwarp();
        }
    }
}

// ---------------- aggregation D=64 fp16: 4 edges per warp (8 lanes x 16B each) ----------------
template <bool BIAS, bool RELU>
__global__ void k_agg64(const __half* __restrict__ H, const float* __restrict__ bias,
                        __half* __restrict__ out) {
    int warp = (blockIdx.x * blockDim.x + threadIdx.x) >> 5;
    int lane = threadIdx.x & 31;
    if (warp >= N_NODES) return;
    int grp = lane >> 3, gl = lane & 7;
    const uint4* H4 = (const uint4*)H;

    float a[8];
#pragma unroll
    for (int j = 0; j < 8; j++) a[j] = 0.f;

    if (grp == 0) {
        float selfn = g_dis[warp];
        selfn *= selfn;
        uint4 v = H4[(size_t)warp * 8 + gl];
        const __half2* h2 = (const __half2*)&v;
#pragma unroll
        for (int j = 0; j < 4; j++) {
            float2 f = __half22float2(h2[j]);
            a[2 * j] = f.x * selfn;
            a[2 * j + 1] = f.y * selfn;
        }
    }

    int s = g_rowptr[warp];
    int e = s + g_cnt[warp];
    for (int p = s + grp; p < e; p += 4) {
        int src = __ldg(&g_col[p]);
        float w = __ldg(&g_val[p]);
        uint4 v = __ldg(&H4[(size_t)src * 8 + gl]);
        const __half2* h2 = (const __half2*)&v;
#pragma unroll
        for (int j = 0; j < 4; j++) {
            float2 f = __half22float2(h2[j]);
            a[2 * j] += f.x * w;
            a[2 * j + 1] += f.y * w;
        }
    }
    __syncwarp();
#pragma unroll
    for (int j = 0; j < 8; j++) {
        a[j] += __shfl_xor_sync(0xffffffffu, a[j], 8);
        a[j] += __shfl_xor_sync(0xffffffffu, a[j], 16);
    }
    if (grp == 0) {
#pragma unroll
        for (int j = 0; j < 8; j++) {
            if (BIAS) a[j] += bias[gl * 8 + j];
            if (RELU) a[j] = fmaxf(a[j], 0.f);
        }
        __half2 h0 = __floats2half2_rn(a[0], a[1]);
        __half2 h1 = __floats2half2_rn(a[2], a[3]);
        __half2 h2o = __floats2half2_rn(a[4], a[5]);
        __half2 h3 = __floats2half2_rn(a[6], a[7]);
        uint4 pk;
        pk.x = *(unsigned*)&h0; pk.y = *(unsigned*)&h1;
        pk.z = *(unsigned*)&h2o; pk.w = *(unsigned*)&h3;
        ((uint4*)out)[(size_t)warp * 8 + gl] = pk;
    }
}

// ---------------- aggregation D=128 fp16 in/out: 2 edges per warp (16 lanes x 16B) ----------------
__global__ void k_agg128(const __half* __restrict__ H, __half* __restrict__ out) {
    int warp = (blockIdx.x * blockDim.x + threadIdx.x) >> 5;
    int lane = threadIdx.x & 31;
    if (warp >= N_NODES) return;
    int half = lane >> 4, hl = lane & 15;
    const uint4* H4 = (const uint4*)H;

    float a[8];
#pragma unroll
    for (int j = 0; j < 8; j++) a[j] = 0.f;

    if (half == 0) {
        float selfn = g_dis[warp];
        selfn *= selfn;
        uint4 v = H4[(size_t)warp * 16 + hl];
        const __half2* h2 = (const __half2*)&v;
#pragma unroll
        for (int j = 0; j < 4; j++) {
            float2 f = __half22float2(h2[j]);
            a[2 * j] = f.x * selfn;
            a[2 * j + 1] = f.y * selfn;
        }
    }

    int s = g_rowptr[warp];
    int e = s + g_cnt[warp];
    for (int p = s + half; p < e; p += 2) {
        int src = __ldg(&g_col[p]);
        float w = __ldg(&g_val[p]);
        uint4 v = __ldg(&H4[(size_t)src * 16 + hl]);
        const __half2* h2 = (const __half2*)&v;
#pragma unroll
        for (int j = 0; j < 4; j++) {
            float2 f = __half22float2(h2[j]);
            a[2 * j] += f.x * w;
            a[2 * j + 1] += f.y * w;
        }
    }
    __syncwarp();
#pragma unroll
    for (int j = 0; j < 8; j++)
        a[j] += __shfl_xor_sync(0xffffffffu, a[j], 16);
    if (half == 0) {
        __half2 h0 = __floats2half2_rn(a[0], a[1]);
        __half2 h1 = __floats2half2_rn(a[2], a[3]);
        __half2 h2o = __floats2half2_rn(a[4], a[5]);
        __half2 h3 = __floats2half2_rn(a[6], a[7]);
        uint4 pk;
        pk.x = *(unsigned*)&h0; pk.y = *(unsigned*)&h1;
        pk.z = *(unsigned*)&h2o; pk.w = *(unsigned*)&h3;
        ((uint4*)out)[(size_t)warp * 16 + hl] = pk;
    }
}

// ---------------- L4 re-association: proj = h3(fp16) @ W45 (N x 3), THEN aggregate at D=3 ----------------
__global__ void k_proj(const __half* __restrict__ H) {
    int warp = (blockIdx.x * blockDim.x + threadIdx.x) >> 5;
    int lane = threadIdx.x & 31;
    if (warp >= N_NODES) return;

    uint4 v = ((const uint4*)H)[(size_t)warp * 32 + lane];
    const __half2* h2 = (const __half2*)&v;
    float s0 = 0.f, s1 = 0.f, s2 = 0.f;
#pragma unroll
    for (int j = 0; j < 4; j++) {
        float2 f = __half22float2(h2[j]);
        int col = 8 * lane + 2 * j;
        s0 += f.x * g_W45[col * 3 + 0] + f.y * g_W45[(col + 1) * 3 + 0];
        s1 += f.x * g_W45[col * 3 + 1] + f.y * g_W45[(col + 1) * 3 + 1];
        s2 += f.x * g_W45[col * 3 + 2] + f.y * g_W45[(col + 1) * 3 + 2];
    }
#pragma unroll
    for (int off = 16; off; off >>= 1) {
        s0 += __shfl_down_sync(0xffffffffu, s0, off);
        s1 += __shfl_down_sync(0xffffffffu, s1, off);
        s2 += __shfl_down_sync(0xffffffffu, s2, off);
    }
    if (lane == 0) g_proj[warp] = make_float4(s0, s1, s2, 0.f);
}

__global__ void k_agg3(float* __restrict__ out) {
    int v = blockIdx.x * blockDim.x + threadIdx.x;
    if (v >= N_NODES) return;
    float selfn = g_dis[v];
    selfn *= selfn;
    float4 p = g_proj[v];
    float a0 = p.x * selfn, a1 = p.y * selfn, a2 = p.z * selfn;

    int s = g_rowptr[v];
    int e = s + g_cnt[v];
#pragma unroll 2
    for (int q = s; q < e; q++) {
        int src = __ldg(&g_col[q]);
        float w = __ldg(&g_val[q]);
        float4 h = __ldg(&g_proj[src]);
        a0 += h.x * w; a1 += h.y * w; a2 += h.z * w;
    }
    out[(size_t)v * 3 + 0] = a0 + g_b45[0];
    out[(size_t)v * 3 + 1] = a1 + g_b45[1];
    out[(size_t)v * 3 + 2] = a2 + g_b45[2];
}

// ---------------- launch ----------------
extern "C" void kernel_launch(void* const* d_in, const int* in_sizes, int n_in,
                              void* d_out, int out_size) {
    const float* x    = (const float*)d_in[0];
    const void*  ei   = d_in[1];
    const float* ew   = (const float*)d_in[2];
    const float* W1   = (const float*)d_in[3];
    const float* b1   = (const float*)d_in[4];
    const float* W2   = (const float*)d_in[5];
    const float* b2   = (const float*)d_in[6];
    const float* W3   = (const float*)d_in[7];
    const float* b3   = (const float*)d_in[8];
    const float* W4   = (const float*)d_in[9];
    const float* b4   = (const float*)d_in[10];
    const float* Wout = (const float*)d_in[11];
    const float* bout = (const float*)d_in[12];
    float* out = (float*)d_out;

    __half *hx, *hA, *hB, *hW1, *hW2, *hW3;
    cudaGetSymbolAddress((void**)&hx, g_hx);
    cudaGetSymbolAddress((void**)&hA, g_hA);
    cudaGetSymbolAddress((void**)&hB, g_hB);
    cudaGetSymbolAddress((void**)&hW1, g_hW1);
    cudaGetSymbolAddress((void**)&hW2, g_hW2);
    cudaGetSymbolAddress((void**)&hW3, g_hW3);

    static cudaStream_t s2 = nullptr;
    static cudaEvent_t evFork = nullptr, evJoin = nullptr, evJoin2 = nullptr;
    if (!s2) {
        cudaStreamCreateWithFlags(&s2, cudaStreamNonBlocking);
        cudaEventCreateWithFlags(&evFork, cudaEventDisableTiming);
        cudaEventCreateWithFlags(&evJoin, cudaEventDisableTiming);
        cudaEventCreateWithFlags(&evJoin2, cudaEventDisableTiming);
    }

    const int TB = 256;
    int nodeBlocks = (N_NODES + TB - 1) / TB;
    int edgeBlocks = (N_EDGES + TB - 1) / TB;
    int scanBlocks = (N_NODES + 1023) / 1024;
    int warpNodeBlocks = (N_NODES + 7) / 8;
    int gm = (N_NODES + 127) / 128;

    // fork: conversions + GEMM1 are needed at the first agg; W45 fold only before k_proj
    cudaEventRecord(evFork, 0);
    cudaStreamWaitEvent(s2, evFork, 0);
    k_cvt<<<(N_NODES * 128 / 8 + TB - 1) / TB, TB, 0, s2>>>(x, hx, N_NODES * 128);
    k_cvtw<<<(49152 / 8 + TB - 1) / TB, TB, 0, s2>>>(W1, W2, W3, hW1, hW2, hW3);
    k_hgemm<<<dim3(gm, 1), 256, 0, s2>>>(hx, hW1, nullptr, hA, 128, 64, 0);
    cudaEventRecord(evJoin, s2);
    k_w45<<<97, 256, 0, s2>>>(W4, b4, Wout, bout);   // off critical path; joined before k_proj
    cudaEventRecord(evJoin2, s2);

    // main stream: CSR preprocessing
    k_init<<<nodeBlocks, TB>>>();
    k_detect<<<(DETECT_WORDS + TB - 1) / TB, TB>>>((const long long*)ei);
    k_decdeg<<<edgeBlocks, TB>>>(ei, ew);
    k_dis<<<nodeBlocks, TB>>>();
    k_scan1<<<scanBlocks, 1024>>>();
    k_scan2<<<1, 128>>>(scanBlocks);
    k_addoff<<<nodeBlocks, TB>>>();
    k_build<<<edgeBlocks, TB>>>(ei, ew);

    cudaStreamWaitEvent(0, evJoin, 0);

    // L1: h1 = relu(agg(t1) + b1)             t1=hA(64) -> h1=hB(64)
    k_agg64<true, true><<<warpNodeBlocks, 256>>>(hA, b1, hB);

    // L2: h2 = relu(agg(h1) @ W2 + b2)        a2=hA(64); t2=hB(128)
    k_agg64<false, false><<<warpNodeBlocks, 256>>>(hB, nullptr, hA);
    k_hgemm<<<dim3(gm, 2), 256>>>(hA, hW2, b2, hB, 64, 128, 1);

    // L3: h3 = relu(agg(h2) @ W3 + b3)        a3=hA(128); t3=hB(256)
    k_agg128<<<warpNodeBlocks, 256>>>(hB, hA);
    k_hgemm<<<dim3(gm, 4), 256>>>(hA, hW3, b3, hB, 128, 256, 1);

    // L4 + head, re-associated: out = agg(h3 @ W45) + b45
    cudaStreamWaitEvent(0, evJoin2, 0);
    k_proj<<<warpNodeBlocks, 256>>>(hB);
    k_agg3<<<nodeBlocks, TB>>>(out);

    (void)in_sizes; (void)n_in; (void)out_size;
}

// round 10
// speedup vs baseline: 2.4294x; 1.0205x over previous
#include <cuda_runtime.h>
#include <cuda_fp16.h>
#include <mma.h>

using namespace nvcuda;

#define N_NODES 100000
#define N_EDGES 1600000

typedef unsigned long long ull;

// ---------------- scratch (__device__ globals; no allocation allowed) ----------------
__device__ float g_deg[N_NODES];
__device__ float g_dis[N_NODES];
__device__ int   g_cnt[N_NODES];
__device__ int   g_rowptr[N_NODES];
__device__ int   g_fill[N_NODES];
__device__ int   g_col[N_EDGES];
__device__ float g_val[N_EDGES];
__device__ int   g_is64;
__device__ int   g_total;
__device__ float g_W45[256 * 3];
__device__ float g_b45[3];
__device__ __half g_hx[(size_t)N_NODES * 128];   // x in fp16
__device__ __half g_hA[(size_t)N_NODES * 256];   // ping
__device__ __half g_hB[(size_t)N_NODES * 256];   // pong
__device__ __half g_hW1[128 * 64];
__device__ __half g_hW2[64 * 128];
__device__ __half g_hW3[128 * 256];
__device__ float4 g_proj[N_NODES];

// ---------------- fused init + dtype detection ----------------
// Detection: interpret first 2048 int64 words. A packed-int32 buffer has word
// values >= 2^32 unless the high int32 is 0 (p ~ 1e-5/word) -> certainty here.
__global__ void k_initdet(const long long* __restrict__ ei) {
    __shared__ int bigfound;
    int i = blockIdx.x * blockDim.x + threadIdx.x;
    if (i < N_NODES) { g_deg[i] = 1.0f; g_cnt[i] = 0; }
    if (blockIdx.x == 0) {
        if (threadIdx.x == 0) { bigfound = 0; g_total = 0; }
        __syncthreads();
        bool big = false;
#pragma unroll
        for (int j = 0; j < 8; j++) {
            ull v = (ull)ei[threadIdx.x * 8 + j];
            if (v >= (ull)N_NODES) big = true;
        }
        if (big) bigfound = 1;
        __syncthreads();
        if (threadIdx.x == 0) g_is64 = bigfound ? 0 : 1;
    }
}

__device__ __forceinline__ void decode_edge(const void* eiv, int e, int& s, int& d) {
    if (g_is64) {
        const long long* ei = (const long long*)eiv;
        s = (int)ei[e];
        d = (int)ei[N_EDGES + e];
    } else {
        const int* ei = (const int*)eiv;
        s = ei[e];
        d = ei[N_EDGES + e];
    }
}

__global__ void k_decdeg(const void* __restrict__ eiv, const float* __restrict__ ew) {
    int e = blockIdx.x * blockDim.x + threadIdx.x;
    if (e >= N_EDGES) return;
    int s, d;
    decode_edge(eiv, e, s, d);
    atomicAdd(&g_deg[d], ew[e]);
    atomicAdd(&g_cnt[d], 1);
}

// fused: dis = rsqrt(deg)  AND  CSR slot allocation (block scan + 1 atomic per block)
__global__ void k_disalloc() {
    __shared__ int s[256];
    __shared__ int sbase;
    int tid = threadIdx.x;
    int i = blockIdx.x * 256 + tid;
    int c = (i < N_NODES) ? g_cnt[i] : 0;
    if (i < N_NODES) g_dis[i] = rsqrtf(g_deg[i]);
    s[tid] = c;
    __syncthreads();
    for (int off = 1; off < 256; off <<= 1) {
        int t = (tid >= off) ? s[tid - off] : 0;
        __syncthreads();
        s[tid] += t;
        __syncthreads();
    }
    if (tid == 255) sbase = atomicAdd(&g_total, s[255]);
    __syncthreads();
    if (i < N_NODES) {
        int r = sbase + s[tid] - c;   // exclusive within block + block base
        g_rowptr[i] = r;
        g_fill[i] = r;
    }
}

__global__ void k_build(const void* __restrict__ eiv, const float* __restrict__ ew) {
    int e = blockIdx.x * blockDim.x + threadIdx.x;
    if (e >= N_EDGES) return;
    int s, d;
    decode_edge(eiv, e, s, d);
    float nm = g_dis[s] * ew[e] * g_dis[d];
    int p = atomicAdd(&g_fill[d], 1);
    g_col[p] = s;
    g_val[p] = nm;
}

// parallel fold: W45[k][c] = sum_j W4[k][j] * Wout[j][c]; one warp per output
__global__ void k_w45(const float* __restrict__ W4, const float* __restrict__ b4,
                      const float* __restrict__ Wout, const float* __restrict__ bout) {
    int gw = (blockIdx.x * blockDim.x + threadIdx.x) >> 5;
    int lane = threadIdx.x & 31;
    if (gw < 768) {
        int k = gw / 3, c = gw % 3;
        float s = 0.f;
#pragma unroll
        for (int j = lane; j < 256; j += 32)
            s += W4[k * 256 + j] * Wout[j * 3 + c];
#pragma unroll
        for (int off = 16; off; off >>= 1)
            s += __shfl_down_sync(0xffffffffu, s, off);
        if (lane == 0) g_W45[gw] = s;
    } else if (gw < 771) {
        int c = gw - 768;
        float s = 0.f;
#pragma unroll
        for (int j = lane; j < 256; j += 32)
            s += b4[j] * Wout[j * 3 + c];
#pragma unroll
        for (int off = 16; off; off >>= 1)
            s += __shfl_down_sync(0xffffffffu, s, off);
        if (lane == 0) g_b45[c] = s + bout[c];
    }
}

// ---------------- fused fp32->fp16: x (12.8M) then W1/W2/W3 (49152) ----------------
#define NX (N_NODES * 128)
__global__ void k_cvtall(const float* __restrict__ x, const float* __restrict__ W1,
                         const float* __restrict__ W2, const float* __restrict__ W3,
                         __half* __restrict__ hx, __half* __restrict__ h1,
                         __half* __restrict__ h2, __half* __restrict__ h3) {
    int i = (blockIdx.x * blockDim.x + threadIdx.x) * 8;
    const float* in;
    __half* out;
    if (i < NX) { in = x; out = hx; }
    else {
        int w = i - NX;
        if (w < 8192) { in = W1; out = h1; i = w; }
        else if (w < 16384) { in = W2; out = h2; i = w - 8192; }
        else if (w < 49152) { in = W3; out = h3; i = w - 16384; }
        else return;
    }
    float4 a = *(const float4*)&in[i];
    float4 b = *(const float4*)&in[i + 4];
    __half2 q0 = __floats2half2_rn(a.x, a.y);
    __half2 q1 = __floats2half2_rn(a.z, a.w);
    __half2 q2 = __floats2half2_rn(b.x, b.y);
    __half2 q3 = __floats2half2_rn(b.z, b.w);
    uint4 pk;
    pk.x = *(unsigned*)&q0; pk.y = *(unsigned*)&q1;
    pk.z = *(unsigned*)&q2; pk.w = *(unsigned*)&q3;
    *(uint4*)&out[i] = pk;
}

// ---------------- HMMA GEMM (wmma): double-buffered, BK=32 ----------------
// block tile 128(M) x 64(N), 256 threads = 8 warps (4m x 2n), warp tile 32x32
__global__ void k_hgemm(const __half* __restrict__ A, const __half* __restrict__ W,
                        const float* __restrict__ bias, __half* __restrict__ C,
                        int din, int dout, int relu) {
    __shared__ __half As[2][128][40];
    __shared__ __half Bs[2][32][72];
    __shared__ float Es[8][256];

    int tid = threadIdx.x;
    int lane = tid & 31;
    int wid = tid >> 5;
    int warp_m = wid & 3;
    int warp_n = wid >> 2;
    int row0 = blockIdx.x * 128;
    int col0 = blockIdx.y * 64;

    int ar0 = tid >> 1, ac0 = (tid & 1) * 8;
    int br = tid >> 3, bc = (tid & 7) * 8;

    wmma::fragment<wmma::accumulator, 16, 16, 16, float> acc[2][2];
#pragma unroll
    for (int i = 0; i < 2; i++)
#pragma unroll
        for (int j = 0; j < 2; j++) wmma::fill_fragment(acc[i][j], 0.f);

    int nk = din >> 5;

    {
        uint4 v0 = make_uint4(0, 0, 0, 0), v1 = v0;
        if (row0 + ar0 < N_NODES) {
            v0 = *(const uint4*)&A[(size_t)(row0 + ar0) * din + ac0];
            v1 = *(const uint4*)&A[(size_t)(row0 + ar0) * din + ac0 + 16];
        }
        *(uint4*)&As[0][ar0][ac0] = v0;
        *(uint4*)&As[0][ar0][ac0 + 16] = v1;
        *(uint4*)&Bs[0][br][bc] = *(const uint4*)&W[(size_t)br * dout + col0 + bc];
    }
    __syncthreads();

    for (int kt = 0; kt < nk; kt++) {
        int cur = kt & 1;
        bool more = (kt + 1 < nk);
        uint4 p0, p1, pb;
        if (more) {
            int k0 = (kt + 1) << 5;
            p0 = make_uint4(0, 0, 0, 0); p1 = p0;
            if (row0 + ar0 < N_NODES) {
                p0 = *(const uint4*)&A[(size_t)(row0 + ar0) * din + k0 + ac0];
                p1 = *(const uint4*)&A[(size_t)(row0 + ar0) * din + k0 + ac0 + 16];
            }
            pb = *(const uint4*)&W[(size_t)(k0 + br) * dout + col0 + bc];
        }
#pragma unroll
        for (int ks = 0; ks < 2; ks++) {
            wmma::fragment<wmma::matrix_a, 16, 16, 16, __half, wmma::row_major> af[2];
            wmma::fragment<wmma::matrix_b, 16, 16, 16, __half, wmma::row_major> bf[2];
#pragma unroll
            for (int i = 0; i < 2; i++)
                wmma::load_matrix_sync(af[i], &As[cur][warp_m * 32 + i * 16][ks * 16], 40);
#pragma unroll
            for (int j = 0; j < 2; j++)
                wmma::load_matrix_sync(bf[j], &Bs[cur][ks * 16][warp_n * 32 + j * 16], 72);
#pragma unroll
            for (int i = 0; i < 2; i++)
#pragma unroll
                for (int j = 0; j < 2; j++)
                    wmma::mma_sync(acc[i][j], af[i], bf[j], acc[i][j]);
        }
        if (more) {
            int nxt = cur ^ 1;
            *(uint4*)&As[nxt][ar0][ac0] = p0;
            *(uint4*)&As[nxt][ar0][ac0 + 16] = p1;
            *(uint4*)&Bs[nxt][br][bc] = pb;
            __syncthreads();
        }
    }

#pragma unroll
    for (int i = 0; i < 2; i++) {
#pragma unroll
        for (int j = 0; j < 2; j++) {
            wmma::store_matrix_sync(&Es[wid][0], acc[i][j], 16, wmma::mem_row_major);
            __syncwarp();
            int r = lane >> 1, c = (lane & 1) * 8;
            int gr = row0 + warp_m * 32 + i * 16 + r;
            int gc = col0 + warp_n * 32 + j * 16 + c;
            if (gr < N_NODES) {
                float v[8];
#pragma unroll
                for (int t = 0; t < 8; t++) {
                    float f = Es[wid][r * 16 + c + t];
                    if (bias) f += bias[gc + t];
                    if (relu) f = fmaxf(f, 0.f);
                    v[t] = f;
                }
                __half2 h0 = __floats2half2_rn(v[0], v[1]);
                __half2 h1 = __floats2half2_rn(v[2], v[3]);
                __half2 h2 = __floats2half2_rn(v[4], v[5]);
                __half2 h3 = __floats2half2_rn(v[6], v[7]);
                uint4 pk;
                pk.x = *(unsigned*)&h0; pk.y = *(unsigned*)&h1;
                pk.z = *(unsigned*)&h2; pk.w = *(unsigned*)&h3;
                *(uint4*)&C[(size_t)gr * dout + gc] = pk;
            }
            __syncwarp();
        }
    }
}

// ---------------- aggregation D=64 fp16: 4 edges per warp (8 lanes x 16B each) ----------------
template <bool BIAS, bool RELU>
__global__ void k_agg64(const __half* __restrict__ H, const float* __restrict__ bias,
                        __half* __restrict__ out) {
    int warp = (blockIdx.x * blockDim.x + threadIdx.x) >> 5;
    int lane = threadIdx.x & 31;
    if (warp >= N_NODES) return;
    int grp = lane >> 3, gl = lane & 7;
    const uint4* H4 = (const uint4*)H;

    float a[8];
#pragma unroll
    for (int j = 0; j < 8; j++) a[j] = 0.f;

    if (grp == 0) {
        float selfn = g_dis[warp];
        selfn *= selfn;
        uint4 v = H4[(size_t)warp * 8 + gl];
        const __half2* h2 = (const __half2*)&v;
#pragma unroll
        for (int j = 0; j < 4; j++) {
            float2 f = __half22float2(h2[j]);
            a[2 * j] = f.x * selfn;
            a[2 * j + 1] = f.y * selfn;
        }
    }

    int s = g_rowptr[warp];
    int e = s + g_cnt[warp];
    for (int p = s + grp; p < e; p += 4) {
        int src = __ldg(&g_col[p]);
        float w = __ldg(&g_val[p]);
        uint4 v = __ldg(&H4[(size_t)src * 8 + gl]);
        const __half2* h2 = (const __half2*)&v;
#pragma unroll
        for (int j = 0; j < 4; j++) {
            float2 f = __half22float2(h2[j]);
            a[2 * j] += f.x * w;
            a[2 * j + 1] += f.y * w;
        }
    }
    __syncwarp();
#pragma unroll
    for (int j = 0; j < 8; j++) {
        a[j] += __shfl_xor_sync(0xffffffffu, a[j], 8);
        a[j] += __shfl_xor_sync(0xffffffffu, a[j], 16);
    }
    if (grp == 0) {
#pragma unroll
        for (int j = 0; j < 8; j++) {
            if (BIAS) a[j] += bias[gl * 8 + j];
            if (RELU) a[j] = fmaxf(a[j], 0.f);
        }
        __half2 h0 = __floats2half2_rn(a[0], a[1]);
        __half2 h1 = __floats2half2_rn(a[2], a[3]);
        __half2 h2o = __floats2half2_rn(a[4], a[5]);
        __half2 h3 = __floats2half2_rn(a[6], a[7]);
        uint4 pk;
        pk.x = *(unsigned*)&h0; pk.y = *(unsigned*)&h1;
        pk.z = *(unsigned*)&h2o; pk.w = *(unsigned*)&h3;
        ((uint4*)out)[(size_t)warp * 8 + gl] = pk;
    }
}

// ---------------- aggregation D=128 fp16 in/out: 2 edges per warp (16 lanes x 16B) ----------------
__global__ void k_agg128(const __half* __restrict__ H, __half* __restrict__ out) {
    int warp = (blockIdx.x * blockDim.x + threadIdx.x) >> 5;
    int lane = threadIdx.x & 31;
    if (warp >= N_NODES) return;
    int half = lane >> 4, hl = lane & 15;
    const uint4* H4 = (const uint4*)H;

    float a[8];
#pragma unroll
    for (int j = 0; j < 8; j++) a[j] = 0.f;

    if (half == 0) {
        float selfn = g_dis[warp];
        selfn *= selfn;
        uint4 v = H4[(size_t)warp * 16 + hl];
        const __half2* h2 = (const __half2*)&v;
#pragma unroll
        for (int j = 0; j < 4; j++) {
            float2 f = __half22float2(h2[j]);
            a[2 * j] = f.x * selfn;
            a[2 * j + 1] = f.y * selfn;
        }
    }

    int s = g_rowptr[warp];
    int e = s + g_cnt[warp];
    for (int p = s + half; p < e; p += 2) {
        int src = __ldg(&g_col[p]);
        float w = __ldg(&g_val[p]);
        uint4 v = __ldg(&H4[(size_t)src * 16 + hl]);
        const __half2* h2 = (const __half2*)&v;
#pragma unroll
        for (int j = 0; j < 4; j++) {
            float2 f = __half22float2(h2[j]);
            a[2 * j] += f.x * w;
            a[2 * j + 1] += f.y * w;
        }
    }
    __syncwarp();
#pragma unroll
    for (int j = 0; j < 8; j++)
        a[j] += __shfl_xor_sync(0xffffffffu, a[j], 16);
    if (half == 0) {
        __half2 h0 = __floats2half2_rn(a[0], a[1]);
        __half2 h1 = __floats2half2_rn(a[2], a[3]);
        __half2 h2o = __floats2half2_rn(a[4], a[5]);
        __half2 h3 = __floats2half2_rn(a[6], a[7]);
        uint4 pk;
        pk.x = *(unsigned*)&h0; pk.y = *(unsigned*)&h1;
        pk.z = *(unsigned*)&h2o; pk.w = *(unsigned*)&h3;
        ((uint4*)out)[(size_t)warp * 16 + hl] = pk;
    }
}

// ---------------- L4 re-association: proj = h3(fp16) @ W45 (N x 3), THEN aggregate at D=3 ----------------
__global__ void k_proj(const __half* __restrict__ H) {
    int warp = (blockIdx.x * blockDim.x + threadIdx.x) >> 5;
    int lane = threadIdx.x & 31;
    if (warp >= N_NODES) return;

    uint4 v = ((const uint4*)H)[(size_t)warp * 32 + lane];
    const __half2* h2 = (const __half2*)&v;
    float s0 = 0.f, s1 = 0.f, s2 = 0.f;
#pragma unroll
    for (int j = 0; j < 4; j++) {
        float2 f = __half22float2(h2[j]);
        int col = 8 * lane + 2 * j;
        s0 += f.x * g_W45[col * 3 + 0] + f.y * g_W45[(col + 1) * 3 + 0];
        s1 += f.x * g_W45[col * 3 + 1] + f.y * g_W45[(col + 1) * 3 + 1];
        s2 += f.x * g_W45[col * 3 + 2] + f.y * g_W45[(col + 1) * 3 + 2];
    }
#pragma unroll
    for (int off = 16; off; off >>= 1) {
        s0 += __shfl_down_sync(0xffffffffu, s0, off);
        s1 += __shfl_down_sync(0xffffffffu, s1, off);
        s2 += __shfl_down_sync(0xffffffffu, s2, off);
    }
    if (lane == 0) g_proj[warp] = make_float4(s0, s1, s2, 0.f);
}

__global__ void k_agg3(float* __restrict__ out) {
    int v = blockIdx.x * blockDim.x + threadIdx.x;
    if (v >= N_NODES) return;
    float selfn = g_dis[v];
    selfn *= selfn;
    float4 p = g_proj[v];
    float a0 = p.x * selfn, a1 = p.y * selfn, a2 = p.z * selfn;

    int s = g_rowptr[v];
    int e = s + g_cnt[v];
#pragma unroll 2
    for (int q = s; q < e; q++) {
        int src = __ldg(&g_col[q]);
        float w = __ldg(&g_val[q]);
        float4 h = __ldg(&g_proj[src]);
        a0 += h.x * w; a1 += h.y * w; a2 += h.z * w;
    }
    out[(size_t)v * 3 + 0] = a0 + g_b45[0];
    out[(size_t)v * 3 + 1] = a1 + g_b45[1];
    out[(size_t)v * 3 + 2] = a2 + g_b45[2];
}

// ---------------- launch ----------------
extern "C" void kernel_launch(void* const* d_in, const int* in_sizes, int n_in,
                              void* d_out, int out_size) {
    const float* x    = (const float*)d_in[0];
    const void*  ei   = d_in[1];
    const float* ew   = (const float*)d_in[2];
    const float* W1   = (const float*)d_in[3];
    const float* b1   = (const float*)d_in[4];
    const float* W2   = (const float*)d_in[5];
    const float* b2   = (const float*)d_in[6];
    const float* W3   = (const float*)d_in[7];
    const float* b3   = (const float*)d_in[8];
    const float* W4   = (const float*)d_in[9];
    const float* b4   = (const float*)d_in[10];
    const float* Wout = (const float*)d_in[11];
    const float* bout = (const float*)d_in[12];
    float* out = (float*)d_out;

    __half *hx, *hA, *hB, *hW1, *hW2, *hW3;
    cudaGetSymbolAddress((void**)&hx, g_hx);
    cudaGetSymbolAddress((void**)&hA, g_hA);
    cudaGetSymbolAddress((void**)&hB, g_hB);
    cudaGetSymbolAddress((void**)&hW1, g_hW1);
    cudaGetSymbolAddress((void**)&hW2, g_hW2);
    cudaGetSymbolAddress((void**)&hW3, g_hW3);

    static cudaStream_t s2 = nullptr;
    static cudaEvent_t evFork = nullptr, evJoin = nullptr, evJoin2 = nullptr;
    if (!s2) {
        cudaStreamCreateWithFlags(&s2, cudaStreamNonBlocking);
        cudaEventCreateWithFlags(&evFork, cudaEventDisableTiming);
        cudaEventCreateWithFlags(&evJoin, cudaEventDisableTiming);
        cudaEventCreateWithFlags(&evJoin2, cudaEventDisableTiming);
    }

    const int TB = 256;
    int nodeBlocks = (N_NODES + TB - 1) / TB;
    int edgeBlocks = (N_EDGES + TB - 1) / TB;
    int warpNodeBlocks = (N_NODES + 7) / 8;
    int gm = (N_NODES + 127) / 128;
    int cvtBlocks = ((NX + 49152) / 8 + TB - 1) / TB;

    // fork: conversions + GEMM1 needed at first agg; W45 fold only before k_proj
    cudaEventRecord(evFork, 0);
    cudaStreamWaitEvent(s2, evFork, 0);
    k_cvtall<<<cvtBlocks, TB, 0, s2>>>(x, W1, W2, W3, hx, hW1, hW2, hW3);
    k_hgemm<<<dim3(gm, 1), 256, 0, s2>>>(hx, hW1, nullptr, hA, 128, 64, 0);
    cudaEventRecord(evJoin, s2);
    k_w45<<<97, 256, 0, s2>>>(W4, b4, Wout, bout);   // off critical path
    cudaEventRecord(evJoin2, s2);

    // main stream: CSR preprocessing (4 kernels)
    k_initdet<<<nodeBlocks, TB>>>((const long long*)ei);
    k_decdeg<<<edgeBlocks, TB>>>(ei, ew);
    k_disalloc<<<nodeBlocks, TB>>>();
    k_build<<<edgeBlocks, TB>>>(ei, ew);

    cudaStreamWaitEvent(0, evJoin, 0);

    // L1: h1 = relu(agg(t1) + b1)             t1=hA(64) -> h1=hB(64)
    k_agg64<true, true><<<warpNodeBlocks, 256>>>(hA, b1, hB);

    // L2: h2 = relu(agg(h1) @ W2 + b2)        a2=hA(64); t2=hB(128)
    k_agg64<false, false><<<warpNodeBlocks, 256>>>(hB, nullptr, hA);
    k_hgemm<<<dim3(gm, 2), 256>>>(hA, hW2, b2, hB, 64, 128, 1);

    // L3: h3 = relu(agg(h2) @ W3 + b3)        a3=hA(128); t3=hB(256)
    k_agg128<<<warpNodeBlocks, 256>>>(hB, hA);
    k_hgemm<<<dim3(gm, 4), 256>>>(hA, hW3, b3, hB, 128, 256, 1);

    // L4 + head, re-associated: out = agg(h3 @ W45) + b45
    cudaStreamWaitEvent(0, evJoin2, 0);
    k_proj<<<warpNodeBlocks, 256>>>(hB);
    k_agg3<<<nodeBlocks, TB>>>(out);

    (void)in_sizes; (void)n_in; (void)out_size;
}